// round 11
// baseline (speedup 1.0000x reference)
#include <cuda_runtime.h>
#include <math.h>
#include <stdint.h>

#define ALPHA_SLOPE 0.2f
#define NEG_INF_F   -9000000000000000.0f

#define BB    16
#define NN    1024
#define FIN   1024
#define FOUT  512
#define MTOT  (BB*NN)        // 16384

// ---------------- scratch: fragment-major tf32 buffers ----------------------
// A-frag (m16n8k8 A): per 16m x 8k block, 128 floats: idx = t*4 + kq*2 + mh,
//   t=(m&7)*4+(k&3), kq=(k>>2)&1, mh=(m>>3)&1
// B-frag (n-major [n][k]): per 8n x 8k block, 64 floats: idx = t*2 + kq,
//   t=(n&7)*4+(k&3), kq=(k>>2)&1
__device__ float d_x_af  [(size_t)MTOT * FIN];         // 64MB
__device__ float d_wt_bf [(size_t)FOUT * FIN];         // 2MB  (W^T as B-frag)
__device__ float d_fcw_bf[(size_t)FOUT * 2 * FOUT];    // 2MB
__device__ float d_h_lin [(size_t)MTOT * FOUT];        // 32MB (tf32-rounded, linear)
__device__ float d_h_af  [(size_t)MTOT * FOUT];        // 32MB (A-frag, K=512)
__device__ float d_ht_bf [(size_t)BB * FOUT * NN];     // 32MB (h^T B-frag per batch)
__device__ float d_att_af[(size_t)MTOT * NN];          // 64MB (A-frag per batch)
__device__ float d_agg_af[(size_t)MTOT * FOUT];        // 32MB (A-frag, K=512)
__device__ float d_f1 [MTOT];
__device__ float d_f2 [MTOT];
__device__ float d_inv[MTOT];

// ---------------- helpers ----------------------------------------------------
__device__ __forceinline__ uint32_t smem_u32(const void* p) {
    uint32_t a;
    asm("{ .reg .u64 t; cvta.to.shared.u64 t, %1; cvt.u32.u64 %0, t; }" : "=r"(a) : "l"(p));
    return a;
}
__device__ __forceinline__ void cp16(uint32_t s, const void* g) {
    asm volatile("cp.async.cg.shared.global [%0], [%1], 16;" :: "r"(s), "l"(g));
}
__device__ __forceinline__ void lds128(uint32_t* r, uint32_t a) {
    asm volatile("ld.shared.v4.b32 {%0,%1,%2,%3}, [%4];"
        : "=r"(r[0]), "=r"(r[1]), "=r"(r[2]), "=r"(r[3]) : "r"(a));
}
__device__ __forceinline__ void lds64(uint32_t* r, uint32_t a) {
    asm volatile("ld.shared.v2.b32 {%0,%1}, [%2];"
        : "=r"(r[0]), "=r"(r[1]) : "r"(a));
}
__device__ __forceinline__ void mmatf32(float* c, const uint32_t* a, const uint32_t* b) {
    asm volatile("mma.sync.aligned.m16n8k8.row.col.f32.tf32.tf32.f32 "
        "{%0,%1,%2,%3}, {%4,%5,%6,%7}, {%8,%9}, {%0,%1,%2,%3};"
        : "+f"(c[0]), "+f"(c[1]), "+f"(c[2]), "+f"(c[3])
        : "r"(a[0]), "r"(a[1]), "r"(a[2]), "r"(a[3]), "r"(b[0]), "r"(b[1]));
}
__device__ __forceinline__ uint32_t tf32b(float x) {
    uint32_t u;
    asm("cvt.rna.tf32.f32 %0, %1;" : "=r"(u) : "f"(x));
    return u;
}
__device__ __forceinline__ uint32_t bfrag_off(uint32_t n, uint32_t k, uint32_t KB8) {
    return ((n >> 3) * KB8 + (k >> 3)) * 64u
         + ((n & 7) * 4 + (k & 3)) * 2u + ((k >> 2) & 1);
}

// ---------------- conversion kernels -----------------------------------------
// x -> A-frag: one block per 16-row group; coalesced read, smem permute, linear write
__global__ void k_cvt_x(const float* __restrict__ x)
{
    extern __shared__ uint32_t sp[];                 // 128 kb blocks x 132 (pad)
    const int tid = threadIdx.x;                     // 256 thr
    const uint32_t m0 = blockIdx.x * 16;
    for (int i = tid; i < 16384; i += 256) {
        uint32_t ml = i >> 10, k = i & 1023;
        float v = x[(size_t)(m0 + ml) * FIN + k];
        uint32_t idx = (k >> 3) * 132u + ((ml & 7) * 4 + (k & 3)) * 4u
                     + ((k >> 2) & 1) * 2u + (ml >> 3);
        sp[idx] = tf32b(v);
    }
    __syncthreads();
    uint4* dst = (uint4*)((uint32_t*)d_x_af + (size_t)(m0 >> 4) * (128u * 128u));
    for (int o4 = tid; o4 < 4096; o4 += 256) {
        uint32_t kb = o4 >> 5, w4 = o4 & 31;
        dst[o4] = *(uint4*)(sp + kb * 132u + w4 * 4u);
    }
}
__global__ void k_cvt_wt(const float* __restrict__ W)    // W[1024][512] -> B-frag [n][k]
{
    uint32_t i = blockIdx.x * 256 + threadIdx.x;
    uint32_t n = i & 511, k = i >> 9;
    ((uint32_t*)d_wt_bf)[bfrag_off(n, k, 128)] = tf32b(W[i]);
}
__global__ void k_cvt_fcw(const float* __restrict__ FCW) // fcw[512][1024] -> B-frag
{
    uint32_t i = blockIdx.x * 256 + threadIdx.x;
    uint32_t n = i >> 10, k = i & 1023;
    ((uint32_t*)d_fcw_bf)[bfrag_off(n, k, 128)] = tf32b(FCW[i]);
}

// ---------------- h -> h^T B-frag: block = (32-f group, batch) ---------------
__global__ void k_trB()
{
    extern __shared__ uint32_t sp[];                 // 4 nb x 128 kb x 64 = 32768 u32
    const int tid = threadIdx.x;                     // 256 thr
    const uint32_t f0 = blockIdx.x * 32, b = blockIdx.y;
    for (int i = tid; i < 32768; i += 256) {
        uint32_t ml = i >> 5, fl = i & 31;
        uint32_t v = ((const uint32_t*)d_h_lin)[(size_t)(b * NN + ml) * FOUT + f0 + fl];
        sp[(fl >> 3) * 8192u + (ml >> 3) * 64u
           + ((fl & 7) * 4 + (ml & 3)) * 2u + ((ml >> 2) & 1)] = v;
    }
    __syncthreads();
    uint4* dst = (uint4*)((uint32_t*)d_ht_bf) + (size_t)b * 131072u
               + (size_t)(f0 >> 3) * 2048u;
    const uint4* src = (const uint4*)sp;
    for (int o4 = tid; o4 < 8192; o4 += 256) dst[o4] = src[o4];
}

// ---------------- f1/f2 ------------------------------------------------------
__global__ void k_f12(const float* __restrict__ a)
{
    int row  = (blockIdx.x * blockDim.x + threadIdx.x) >> 5;
    int lane = threadIdx.x & 31;
    if (row >= MTOT) return;
    const float* hr = d_h_lin + (size_t)row * FOUT;
    float s1 = 0.f, s2 = 0.f;
    for (int k = lane; k < FOUT; k += 32) {
        float hv = hr[k];
        s1 = fmaf(hv, a[k], s1);
        s2 = fmaf(hv, a[FOUT + k], s2);
    }
    #pragma unroll
    for (int o = 16; o; o >>= 1) {
        s1 += __shfl_xor_sync(0xffffffffu, s1, o);
        s2 += __shfl_xor_sync(0xffffffffu, s2, o);
    }
    if (lane == 0) { d_f1[row] = s1; d_f2[row] = s2; }
}

// ---------------- attention: warp-per-row softmax, block frag write ----------
__global__ void k_att(const int* __restrict__ adj)
{
    extern __shared__ uint32_t sp[];                 // 128 kb x 132 (pad)
    const int tid = threadIdx.x;                     // 256 thr
    const int wid = tid >> 5, lane = tid & 31;
    const uint32_t row0 = blockIdx.x * 16;
    const uint32_t b = row0 >> 10, mg = (row0 & 1023) >> 4;

    for (int rr = wid; rr < 16; rr += 8) {
        const uint32_t row = row0 + rr;
        const float f1i = d_f1[row];
        const int*   arow = adj + (size_t)row * NN;
        const float* f2b  = d_f2 + b * NN;
        const uint32_t ib = ((rr & 7) * 4) * 4u + (rr >> 3);
        float lmax = -INFINITY;
        for (int j = lane; j < NN; j += 32) {
            float e = f1i + f2b[j];
            e = e > 0.f ? e : ALPHA_SLOPE * e;
            e = (arow[j] > 0) ? e : NEG_INF_F;
            sp[(j >> 3) * 132u + ib + (j & 3) * 4u + ((j >> 2) & 1) * 2u] = __float_as_uint(e);
            lmax = fmaxf(lmax, e);
        }
        #pragma unroll
        for (int o = 16; o; o >>= 1) lmax = fmaxf(lmax, __shfl_xor_sync(0xffffffffu, lmax, o));
        float lsum = 0.f;
        for (int j = lane; j < NN; j += 32) {
            uint32_t idx = (j >> 3) * 132u + ib + (j & 3) * 4u + ((j >> 2) & 1) * 2u;
            float p = __expf(__uint_as_float(sp[idx]) - lmax);
            sp[idx] = tf32b(p);
            lsum += p;
        }
        #pragma unroll
        for (int o = 16; o; o >>= 1) lsum += __shfl_xor_sync(0xffffffffu, lsum, o);
        if (lane == 0) d_inv[row] = 1.f / lsum;
    }
    __syncthreads();
    uint4* dst = (uint4*)((uint32_t*)d_att_af + (size_t)b * NN * NN + (size_t)mg * 16384u);
    for (int o4 = tid; o4 < 4096; o4 += 256) {
        uint32_t kb = o4 >> 5, w4 = o4 & 31;
        dst[o4] = *(uint4*)(sp + kb * 132u + w4 * 4u);
    }
}

// ---------------- tf32 mma GEMM: 128x128 tile, 4 warps of 64x64, BK=32 -------
#define A_TILE_B 16384
#define STAGE_B  32768
#define NSTAGE   3
#define SM_BYTES (NSTAGE * STAGE_B)    // 98304 -> 2 CTAs/SM

template<int MODE>
__global__ __launch_bounds__(128, 2)
void k_tc(const float* __restrict__ fcb, float* __restrict__ outp)
{
    extern __shared__ char smem[];
    const uint32_t sb = smem_u32(smem);
    const int tid = threadIdx.x;
    const int wid = tid >> 5, lane = tid & 31;
    const int wm = wid & 1, wn = wid >> 1;       // 2 x 2 warp grid; warp tile 64m x 64n

    const int n0 = blockIdx.x * 128;
    const int m0 = blockIdx.y * 128;             // local row for MODE 2, global else
    const int b  = (MODE == 2) ? blockIdx.z : (m0 >> 10);

    float acc[4][8][4] = {};
    const int NIT = 32;                          // K = 1024, BK = 32

    const float *Ap1, *Ap2, *Bp;
    uint32_t KA8;
    if (MODE == 1) {
        Ap1 = d_x_af;  Ap2 = Ap1; Bp = d_wt_bf;  KA8 = 128;
    } else if (MODE == 2) {
        Ap1 = d_att_af + (uint32_t)b * (NN * NN); Ap2 = Ap1;
        Bp  = d_ht_bf  + (uint32_t)b * (FOUT * NN); KA8 = 128;
    } else {
        Ap1 = d_agg_af; Ap2 = d_h_af; Bp = d_fcw_bf; KA8 = 64;
    }

    uint32_t a_base0, a_dst0, b_base0, b_dst0;
    {
        uint32_t blk = (uint32_t)tid >> 5, w = (uint32_t)tid & 31;
        uint32_t mb = blk >> 2, kb = blk & 3;
        a_base0 = (((uint32_t)(m0 >> 4) + mb) * KA8 + kb) * 128u + w * 4u;
        a_dst0  = blk * 512u + w * 16u;
        blk = (uint32_t)tid >> 4; w = (uint32_t)tid & 15;
        uint32_t nb = blk >> 2, kbb = blk & 3;
        b_base0 = (((uint32_t)(n0 >> 3) + nb) * 128u + kbb) * 64u + w * 4u;
        b_dst0  = A_TILE_B + blk * 256u + w * 16u;
    }
    const uint32_t a_bstride = KA8 * 128u;

    auto issue = [&](int c) {
        const uint32_t st = sb + (c % NSTAGE) * STAGE_B;
        const float* Ap = (MODE == 3 && c >= 16) ? Ap2 : Ap1;
        const uint32_t ca = (MODE == 3) ? (uint32_t)(c & 15) * 512u : (uint32_t)c * 512u;
        const uint32_t cb = (uint32_t)c * 256u;
        #pragma unroll
        for (uint32_t j = 0; j < 8; j++)
            cp16(st + a_dst0 + j * 2048u, Ap + a_base0 + j * a_bstride + ca);
        #pragma unroll
        for (uint32_t j = 0; j < 8; j++)
            cp16(st + b_dst0 + j * 2048u, Bp + b_base0 + j * 16384u + cb);
        asm volatile("cp.async.commit_group;" ::: "memory");
    };

    const uint32_t a_lds = (uint32_t)lane * 16u;
    const uint32_t b_lds = A_TILE_B + (uint32_t)lane * 8u;

    issue(0);
    issue(1);
    #pragma unroll 1
    for (int c = 0; c < NIT; c++) {
        if (c == NIT - 1) asm volatile("cp.async.wait_group 0;" ::: "memory");
        else              asm volatile("cp.async.wait_group 1;" ::: "memory");
        __syncthreads();
        if (c + 2 < NIT) issue(c + 2);

        const uint32_t base = sb + (c % NSTAGE) * STAGE_B;
        #pragma unroll
        for (int ks = 0; ks < 4; ks++) {
            uint32_t bf[8][2];
            #pragma unroll
            for (int nt = 0; nt < 8; nt++)
                lds64(bf[nt], base + b_lds + ((wn * 8 + nt) * 4 + ks) * 256u);
            #pragma unroll
            for (int mt = 0; mt < 4; mt++) {
                uint32_t af[4];
                lds128(af, base + a_lds + ((wm * 4 + mt) * 4 + ks) * 512u);
                #pragma unroll
                for (int nt = 0; nt < 8; nt++) mmatf32(acc[mt][nt], af, bf[nt]);
            }
        }
    }

    __syncthreads();

    // ---------------- epilogue: smem-staged, bulk-linear global writes -------
    const int g = lane >> 2, tig = lane & 3;
    float* stg = (float*)smem;

    if (MODE == 1 || MODE == 2) {
        // phase A: A-frag tile stage (8 mg x 16 kb x 128, no pad)
        #pragma unroll
        for (int mt = 0; mt < 4; mt++) {
            const int lr0 = wm * 64 + mt * 16 + g;
            float s0 = 1.f, s1 = 1.f;
            if (MODE == 2) {
                s0 = d_inv[b * NN + m0 + lr0];
                s1 = d_inv[b * NN + m0 + lr0 + 8];
            }
            #pragma unroll
            for (int nt = 0; nt < 8; nt++) {
                float* c = acc[mt][nt];
                const uint32_t kb_l = wn * 8 + nt;
                const uint32_t t0 = g * 4 + ((tig * 2) & 3);
                const uint32_t basei = ((uint32_t)(wm * 4 + mt) * 16 + kb_l) * 128u
                                     + (uint32_t)(tig >> 1) * 2u;
                stg[basei + t0 * 4 + 0]       = __uint_as_float(tf32b(c[0] * s0));
                stg[basei + (t0 + 1) * 4 + 0] = __uint_as_float(tf32b(c[1] * s0));
                stg[basei + t0 * 4 + 1]       = __uint_as_float(tf32b(c[2] * s1));
                stg[basei + (t0 + 1) * 4 + 1] = __uint_as_float(tf32b(c[3] * s1));
            }
        }
        __syncthreads();
        const uint32_t MGb = (MODE == 2) ? (uint32_t)(b * NN + m0) >> 4 : (uint32_t)m0 >> 4;
        uint4* gdst = (uint4*)((MODE == 1) ? (uint32_t*)d_h_af : (uint32_t*)d_agg_af);
        for (int o4 = tid; o4 < 4096; o4 += 128) {
            uint32_t mg_l = o4 >> 9, rest = o4 & 511;
            gdst[(size_t)(MGb + mg_l) * 2048u + ((uint32_t)n0 >> 3) * 32u + rest] =
                *(uint4*)(stg + (size_t)o4 * 4u);
        }
        __syncthreads();
    }

    if (MODE == 1 || MODE == 3) {
        // phase B: linear 128x128 tile (row pad 132)
        #pragma unroll
        for (int mt = 0; mt < 4; mt++) {
            const int lr0 = wm * 64 + mt * 16 + g;
            const int lr1 = lr0 + 8;
            #pragma unroll
            for (int nt = 0; nt < 8; nt++) {
                float* c = acc[mt][nt];
                const int lc = wn * 64 + nt * 8 + tig * 2;
                float v0, v1, v2, v3;
                if (MODE == 1) {
                    v0 = __uint_as_float(tf32b(c[0]));
                    v1 = __uint_as_float(tf32b(c[1]));
                    v2 = __uint_as_float(tf32b(c[2]));
                    v3 = __uint_as_float(tf32b(c[3]));
                } else {
                    float b0 = fcb[n0 + lc], b1 = fcb[n0 + lc + 1];
                    v0 = c[0] + b0; v0 = v0 > 0.f ? v0 : expm1f(v0);
                    v1 = c[1] + b1; v1 = v1 > 0.f ? v1 : expm1f(v1);
                    v2 = c[2] + b0; v2 = v2 > 0.f ? v2 : expm1f(v2);
                    v3 = c[3] + b1; v3 = v3 > 0.f ? v3 : expm1f(v3);
                }
                stg[lr0 * 132 + lc] = v0; stg[lr0 * 132 + lc + 1] = v1;
                stg[lr1 * 132 + lc] = v2; stg[lr1 * 132 + lc + 1] = v3;
            }
        }
        __syncthreads();
        float* gdst = (MODE == 1) ? d_h_lin : outp;
        for (int o4 = tid; o4 < 4096; o4 += 128) {
            uint32_t r = o4 >> 5, w4 = o4 & 31;
            *(uint4*)(gdst + (size_t)(m0 + r) * FOUT + n0 + w4 * 4u) =
                *(uint4*)(stg + r * 132u + w4 * 4u);
        }
    }
}

// ---------------- launch -----------------------------------------------------
extern "C" void kernel_launch(void* const* d_in, const int* in_sizes, int n_in,
                              void* d_out, int out_size)
{
    const float* x   = (const float*)d_in[0];
    const int*   adj = (const int*)  d_in[1];
    const float* W   = (const float*)d_in[2];
    const float* a   = (const float*)d_in[3];
    const float* fcw = (const float*)d_in[4];
    const float* fcb = (const float*)d_in[5];
    float* out = (float*)d_out;

    cudaFuncSetAttribute(k_tc<1>, cudaFuncAttributeMaxDynamicSharedMemorySize, SM_BYTES);
    cudaFuncSetAttribute(k_tc<2>, cudaFuncAttributeMaxDynamicSharedMemorySize, SM_BYTES);
    cudaFuncSetAttribute(k_tc<3>, cudaFuncAttributeMaxDynamicSharedMemorySize, SM_BYTES);
    cudaFuncSetAttribute(k_cvt_x, cudaFuncAttributeMaxDynamicSharedMemorySize, 67584);
    cudaFuncSetAttribute(k_att,   cudaFuncAttributeMaxDynamicSharedMemorySize, 67584);
    cudaFuncSetAttribute(k_trB,   cudaFuncAttributeMaxDynamicSharedMemorySize, 131072);

    // conversions to fragment-major tf32
    k_cvt_x  <<<MTOT / 16, 256, 67584>>>(x);
    k_cvt_wt <<<(FIN * FOUT) / 256, 256>>>(W);
    k_cvt_fcw<<<(FOUT * 2 * FOUT) / 256, 256>>>(fcw);

    // 1) h = x @ W  (writes h A-frag + h linear)
    k_tc<1><<<dim3(FOUT / 128, MTOT / 128), 128, SM_BYTES>>>(nullptr, nullptr);
    // 1b) h^T per batch (B-frag)
    k_trB<<<dim3(FOUT / 32, BB), 256, 131072>>>();
    // 2) f1, f2
    k_f12<<<(MTOT * 32) / 256, 256>>>(a);
    // 3) attention numerators (A-frag) + inverse row sums
    k_att<<<MTOT / 16, 256, 67584>>>(adj);
    // 4) agg = softmax(att) @ h
    k_tc<2><<<dim3(FOUT / 128, NN / 128, BB), 128, SM_BYTES>>>(nullptr, nullptr);
    // 5) out = elu([agg, h] @ fc_w^T + fc_b)
    k_tc<3><<<dim3(FOUT / 128, MTOT / 128), 128, SM_BYTES>>>(fcb, out);
}

// round 12
// speedup vs baseline: 1.0379x; 1.0379x over previous
#include <cuda_runtime.h>
#include <math.h>
#include <stdint.h>

#define ALPHA_SLOPE 0.2f
#define NEG_INF_F   -9000000000000000.0f

#define BB    16
#define NN    1024
#define FIN   1024
#define FOUT  512
#define MTOT  (BB*NN)        // 16384

// ---------------- scratch: fragment-major tf32 buffers ----------------------
// A-frag (m16n8k8 A): per 16m x 8k block, 128 floats: idx = t*4 + kq*2 + mh,
//   t=(m&7)*4+(k&3), kq=(k>>2)&1, mh=(m>>3)&1
// B-frag (n-major [n][k]): per 8n x 8k block, 64 floats: idx = t*2 + kq,
//   t=(n&7)*4+(k&3), kq=(k>>2)&1
__device__ float d_x_af  [(size_t)MTOT * FIN];         // 64MB
__device__ float d_wt_bf [(size_t)FOUT * FIN];         // 2MB  (W^T as B-frag)
__device__ float d_fcw_bf[(size_t)FOUT * 2 * FOUT];    // 2MB
__device__ float d_h_lin [(size_t)MTOT * FOUT];        // 32MB (tf32-rounded, linear)
__device__ float d_h_af  [(size_t)MTOT * FOUT];        // 32MB (A-frag, K=512)
__device__ float d_ht_bf [(size_t)BB * FOUT * NN];     // 32MB (h^T B-frag per batch)
__device__ float d_att_af[(size_t)MTOT * NN];          // 64MB (A-frag per batch)
__device__ float d_agg_af[(size_t)MTOT * FOUT];        // 32MB (A-frag, K=512)
__device__ float d_f1 [MTOT];
__device__ float d_f2 [MTOT];
__device__ float d_inv[MTOT];

// ---------------- helpers ----------------------------------------------------
__device__ __forceinline__ uint32_t smem_u32(const void* p) {
    uint32_t a;
    asm("{ .reg .u64 t; cvta.to.shared.u64 t, %1; cvt.u32.u64 %0, t; }" : "=r"(a) : "l"(p));
    return a;
}
__device__ __forceinline__ void cp16(uint32_t s, const void* g) {
    asm volatile("cp.async.cg.shared.global [%0], [%1], 16;" :: "r"(s), "l"(g));
}
__device__ __forceinline__ void lds128(uint32_t* r, uint32_t a) {
    asm volatile("ld.shared.v4.b32 {%0,%1,%2,%3}, [%4];"
        : "=r"(r[0]), "=r"(r[1]), "=r"(r[2]), "=r"(r[3]) : "r"(a));
}
__device__ __forceinline__ void lds64(uint32_t* r, uint32_t a) {
    asm volatile("ld.shared.v2.b32 {%0,%1}, [%2];"
        : "=r"(r[0]), "=r"(r[1]) : "r"(a));
}
__device__ __forceinline__ void mmatf32(float* c, const uint32_t* a, const uint32_t* b) {
    asm volatile("mma.sync.aligned.m16n8k8.row.col.f32.tf32.tf32.f32 "
        "{%0,%1,%2,%3}, {%4,%5,%6,%7}, {%8,%9}, {%0,%1,%2,%3};"
        : "+f"(c[0]), "+f"(c[1]), "+f"(c[2]), "+f"(c[3])
        : "r"(a[0]), "r"(a[1]), "r"(a[2]), "r"(a[3]), "r"(b[0]), "r"(b[1]));
}
__device__ __forceinline__ uint32_t tf32b(float x) {
    uint32_t u;
    asm("cvt.rna.tf32.f32 %0, %1;" : "=r"(u) : "f"(x));
    return u;
}
__device__ __forceinline__ uint32_t bfrag_off(uint32_t n, uint32_t k, uint32_t KB8) {
    return ((n >> 3) * KB8 + (k >> 3)) * 64u
         + ((n & 7) * 4 + (k & 3)) * 2u + ((k >> 2) & 1);
}

#define FRAG_PAD 136u   // kb-block stride in smem words (136 % 32 == 8 -> <=2-way conflicts)

// ---------------- conversion kernels -----------------------------------------
// x -> A-frag: one block per 16-row group; coalesced read, smem permute, linear write
__global__ void k_cvt_x(const float* __restrict__ x)
{
    extern __shared__ uint32_t sp[];                 // 128 kb blocks x FRAG_PAD
    const int tid = threadIdx.x;                     // 256 thr
    const uint32_t m0 = blockIdx.x * 16;
    for (int i = tid; i < 16384; i += 256) {
        uint32_t ml = i >> 10, k = i & 1023;
        float v = x[(size_t)(m0 + ml) * FIN + k];
        uint32_t idx = (k >> 3) * FRAG_PAD + ((ml & 7) * 4 + (k & 3)) * 4u
                     + ((k >> 2) & 1) * 2u + (ml >> 3);
        sp[idx] = tf32b(v);
    }
    __syncthreads();
    uint4* dst = (uint4*)((uint32_t*)d_x_af + (size_t)(m0 >> 4) * (128u * 128u));
    for (int o4 = tid; o4 < 4096; o4 += 256) {
        uint32_t kb = o4 >> 5, w4 = o4 & 31;
        dst[o4] = *(uint4*)(sp + kb * FRAG_PAD + w4 * 4u);
    }
}
__global__ void k_cvt_wt(const float* __restrict__ W)    // W[1024][512] -> B-frag [n][k]
{
    uint32_t i = blockIdx.x * 256 + threadIdx.x;
    uint32_t n = i & 511, k = i >> 9;
    ((uint32_t*)d_wt_bf)[bfrag_off(n, k, 128)] = tf32b(W[i]);
}
__global__ void k_cvt_fcw(const float* __restrict__ FCW) // fcw[512][1024] -> B-frag
{
    uint32_t i = blockIdx.x * 256 + threadIdx.x;
    uint32_t n = i >> 10, k = i & 1023;
    ((uint32_t*)d_fcw_bf)[bfrag_off(n, k, 128)] = tf32b(FCW[i]);
}

// ---------------- h -> h^T B-frag: block = (32-f group, batch) ---------------
__global__ void k_trB()
{
    extern __shared__ uint32_t sp[];                 // 4 nb x 128 kb x 64 = 32768 u32
    const int tid = threadIdx.x;                     // 256 thr
    const uint32_t f0 = blockIdx.x * 32, b = blockIdx.y;
    for (int i = tid; i < 32768; i += 256) {
        uint32_t ml = i >> 5, fl = i & 31;
        uint32_t v = ((const uint32_t*)d_h_lin)[(size_t)(b * NN + ml) * FOUT + f0 + fl];
        sp[(fl >> 3) * 8192u + (ml >> 3) * 64u
           + ((fl & 7) * 4 + (ml & 3)) * 2u + ((ml >> 2) & 1)] = v;
    }
    __syncthreads();
    uint4* dst = (uint4*)((uint32_t*)d_ht_bf) + (size_t)b * 131072u
               + (size_t)(f0 >> 3) * 2048u;
    const uint4* src = (const uint4*)sp;
    for (int o4 = tid; o4 < 8192; o4 += 256) dst[o4] = src[o4];
}

// ---------------- f1/f2 ------------------------------------------------------
__global__ void k_f12(const float* __restrict__ a)
{
    int row  = (blockIdx.x * blockDim.x + threadIdx.x) >> 5;
    int lane = threadIdx.x & 31;
    if (row >= MTOT) return;
    const float* hr = d_h_lin + (size_t)row * FOUT;
    float s1 = 0.f, s2 = 0.f;
    for (int k = lane; k < FOUT; k += 32) {
        float hv = hr[k];
        s1 = fmaf(hv, a[k], s1);
        s2 = fmaf(hv, a[FOUT + k], s2);
    }
    #pragma unroll
    for (int o = 16; o; o >>= 1) {
        s1 += __shfl_xor_sync(0xffffffffu, s1, o);
        s2 += __shfl_xor_sync(0xffffffffu, s2, o);
    }
    if (lane == 0) { d_f1[row] = s1; d_f2[row] = s2; }
}

// ---------------- attention: 512 thr, one warp per row, block frag write -----
__global__ void k_att(const int* __restrict__ adj)
{
    extern __shared__ uint32_t sp[];                 // 128 kb x FRAG_PAD
    const int tid = threadIdx.x;                     // 512 thr
    const int wid = tid >> 5, lane = tid & 31;       // wid = local row 0..15
    const uint32_t row0 = blockIdx.x * 16;
    const uint32_t b = row0 >> 10, mg = (row0 & 1023) >> 4;

    {
        const uint32_t row = row0 + wid;
        const float f1i = d_f1[row];
        const int*   arow = adj + (size_t)row * NN;
        const float* f2b  = d_f2 + b * NN;
        const uint32_t ib = ((uint32_t)(wid & 7) * 4) * 4u + ((uint32_t)wid >> 3);
        float lmax = -INFINITY;
        for (int j = lane; j < NN; j += 32) {
            float e = f1i + f2b[j];
            e = e > 0.f ? e : ALPHA_SLOPE * e;
            e = (arow[j] > 0) ? e : NEG_INF_F;
            sp[(j >> 3) * FRAG_PAD + ib + (j & 3) * 4u + ((j >> 2) & 1) * 2u] = __float_as_uint(e);
            lmax = fmaxf(lmax, e);
        }
        #pragma unroll
        for (int o = 16; o; o >>= 1) lmax = fmaxf(lmax, __shfl_xor_sync(0xffffffffu, lmax, o));
        float lsum = 0.f;
        for (int j = lane; j < NN; j += 32) {
            uint32_t idx = (j >> 3) * FRAG_PAD + ib + (j & 3) * 4u + ((j >> 2) & 1) * 2u;
            float p = __expf(__uint_as_float(sp[idx]) - lmax);
            sp[idx] = tf32b(p);
            lsum += p;
        }
        #pragma unroll
        for (int o = 16; o; o >>= 1) lsum += __shfl_xor_sync(0xffffffffu, lsum, o);
        if (lane == 0) d_inv[row] = 1.f / lsum;
    }
    __syncthreads();
    uint4* dst = (uint4*)((uint32_t*)d_att_af + (size_t)b * NN * NN + (size_t)mg * 16384u);
    for (int o4 = tid; o4 < 4096; o4 += 512) {
        uint32_t kb = o4 >> 5, w4 = o4 & 31;
        dst[o4] = *(uint4*)(sp + kb * FRAG_PAD + w4 * 4u);
    }
}

// ---------------- tf32 mma GEMM: 128x128 tile, 4 warps of 64x64, BK=32 -------
#define A_TILE_B 16384
#define STAGE_B  32768
#define NSTAGE   3
#define SM_BYTES (NSTAGE * STAGE_B)    // 98304 -> 2 CTAs/SM

template<int MODE>
__global__ __launch_bounds__(128, 2)
void k_tc(const float* __restrict__ fcb, float* __restrict__ outp)
{
    extern __shared__ char smem[];
    const uint32_t sb = smem_u32(smem);
    const int tid = threadIdx.x;
    const int wid = tid >> 5, lane = tid & 31;
    const int wm = wid & 1, wn = wid >> 1;       // 2 x 2 warp grid; warp tile 64m x 64n

    const int n0 = blockIdx.x * 128;
    const int m0 = blockIdx.y * 128;             // local row for MODE 2, global else
    const int b  = (MODE == 2) ? blockIdx.z : (m0 >> 10);

    float acc[4][8][4] = {};
    const int NIT = 32;                          // K = 1024, BK = 32

    const float *Ap1, *Ap2, *Bp;
    uint32_t KA8;
    if (MODE == 1) {
        Ap1 = d_x_af;  Ap2 = Ap1; Bp = d_wt_bf;  KA8 = 128;
    } else if (MODE == 2) {
        Ap1 = d_att_af + (uint32_t)b * (NN * NN); Ap2 = Ap1;
        Bp  = d_ht_bf  + (uint32_t)b * (FOUT * NN); KA8 = 128;
    } else {
        Ap1 = d_agg_af; Ap2 = d_h_af; Bp = d_fcw_bf; KA8 = 64;
    }

    uint32_t a_base0, a_dst0, b_base0, b_dst0;
    {
        uint32_t blk = (uint32_t)tid >> 5, w = (uint32_t)tid & 31;
        uint32_t mb = blk >> 2, kb = blk & 3;
        a_base0 = (((uint32_t)(m0 >> 4) + mb) * KA8 + kb) * 128u + w * 4u;
        a_dst0  = blk * 512u + w * 16u;
        blk = (uint32_t)tid >> 4; w = (uint32_t)tid & 15;
        uint32_t nb = blk >> 2, kbb = blk & 3;
        b_base0 = (((uint32_t)(n0 >> 3) + nb) * 128u + kbb) * 64u + w * 4u;
        b_dst0  = A_TILE_B + blk * 256u + w * 16u;
    }
    const uint32_t a_bstride = KA8 * 128u;

    auto issue = [&](int c) {
        const uint32_t st = sb + (c % NSTAGE) * STAGE_B;
        const float* Ap = (MODE == 3 && c >= 16) ? Ap2 : Ap1;
        const uint32_t ca = (MODE == 3) ? (uint32_t)(c & 15) * 512u : (uint32_t)c * 512u;
        const uint32_t cb = (uint32_t)c * 256u;
        #pragma unroll
        for (uint32_t j = 0; j < 8; j++)
            cp16(st + a_dst0 + j * 2048u, Ap + a_base0 + j * a_bstride + ca);
        #pragma unroll
        for (uint32_t j = 0; j < 8; j++)
            cp16(st + b_dst0 + j * 2048u, Bp + b_base0 + j * 16384u + cb);
        asm volatile("cp.async.commit_group;" ::: "memory");
    };

    const uint32_t a_lds = (uint32_t)lane * 16u;
    const uint32_t b_lds = A_TILE_B + (uint32_t)lane * 8u;

    issue(0);
    issue(1);
    #pragma unroll 1
    for (int c = 0; c < NIT; c++) {
        if (c == NIT - 1) asm volatile("cp.async.wait_group 0;" ::: "memory");
        else              asm volatile("cp.async.wait_group 1;" ::: "memory");
        __syncthreads();
        if (c + 2 < NIT) issue(c + 2);

        const uint32_t base = sb + (c % NSTAGE) * STAGE_B;
        #pragma unroll
        for (int ks = 0; ks < 4; ks++) {
            uint32_t bf[8][2];
            #pragma unroll
            for (int nt = 0; nt < 8; nt++)
                lds64(bf[nt], base + b_lds + ((wn * 8 + nt) * 4 + ks) * 256u);
            #pragma unroll
            for (int mt = 0; mt < 4; mt++) {
                uint32_t af[4];
                lds128(af, base + a_lds + ((wm * 4 + mt) * 4 + ks) * 512u);
                #pragma unroll
                for (int nt = 0; nt < 8; nt++) mmatf32(acc[mt][nt], af, bf[nt]);
            }
        }
    }

    __syncthreads();

    // ---------------- epilogue: smem-staged, bulk-linear global writes -------
    const int g = lane >> 2, tig = lane & 3;
    float* stg = (float*)smem;

    if (MODE == 1 || MODE == 2) {
        // phase A: A-frag tile stage (8 mg x 16 kb x 128, no pad)
        #pragma unroll
        for (int mt = 0; mt < 4; mt++) {
            const int lr0 = wm * 64 + mt * 16 + g;
            float s0 = 1.f, s1 = 1.f;
            if (MODE == 2) {
                s0 = d_inv[b * NN + m0 + lr0];
                s1 = d_inv[b * NN + m0 + lr0 + 8];
            }
            #pragma unroll
            for (int nt = 0; nt < 8; nt++) {
                float* c = acc[mt][nt];
                const uint32_t kb_l = wn * 8 + nt;
                const uint32_t t0 = g * 4 + ((tig * 2) & 3);
                const uint32_t basei = ((uint32_t)(wm * 4 + mt) * 16 + kb_l) * 128u
                                     + (uint32_t)(tig >> 1) * 2u;
                stg[basei + t0 * 4 + 0]       = __uint_as_float(tf32b(c[0] * s0));
                stg[basei + (t0 + 1) * 4 + 0] = __uint_as_float(tf32b(c[1] * s0));
                stg[basei + t0 * 4 + 1]       = __uint_as_float(tf32b(c[2] * s1));
                stg[basei + (t0 + 1) * 4 + 1] = __uint_as_float(tf32b(c[3] * s1));
            }
        }
        __syncthreads();
        const uint32_t MGb = (MODE == 2) ? (uint32_t)(b * NN + m0) >> 4 : (uint32_t)m0 >> 4;
        uint4* gdst = (uint4*)((MODE == 1) ? (uint32_t*)d_h_af : (uint32_t*)d_agg_af);
        for (int o4 = tid; o4 < 4096; o4 += 128) {
            uint32_t mg_l = o4 >> 9, rest = o4 & 511;
            gdst[(size_t)(MGb + mg_l) * 2048u + ((uint32_t)n0 >> 3) * 32u + rest] =
                *(uint4*)(stg + (size_t)o4 * 4u);
        }
        __syncthreads();
    }

    if (MODE == 1 || MODE == 3) {
        // phase B: linear 128x128 tile (row pad 132)
        #pragma unroll
        for (int mt = 0; mt < 4; mt++) {
            const int lr0 = wm * 64 + mt * 16 + g;
            const int lr1 = lr0 + 8;
            #pragma unroll
            for (int nt = 0; nt < 8; nt++) {
                float* c = acc[mt][nt];
                const int lc = wn * 64 + nt * 8 + tig * 2;
                float v0, v1, v2, v3;
                if (MODE == 1) {
                    v0 = __uint_as_float(tf32b(c[0]));
                    v1 = __uint_as_float(tf32b(c[1]));
                    v2 = __uint_as_float(tf32b(c[2]));
                    v3 = __uint_as_float(tf32b(c[3]));
                } else {
                    float b0 = fcb[n0 + lc], b1 = fcb[n0 + lc + 1];
                    v0 = c[0] + b0; v0 = v0 > 0.f ? v0 : expm1f(v0);
                    v1 = c[1] + b1; v1 = v1 > 0.f ? v1 : expm1f(v1);
                    v2 = c[2] + b0; v2 = v2 > 0.f ? v2 : expm1f(v2);
                    v3 = c[3] + b1; v3 = v3 > 0.f ? v3 : expm1f(v3);
                }
                stg[lr0 * 132 + lc] = v0; stg[lr0 * 132 + lc + 1] = v1;
                stg[lr1 * 132 + lc] = v2; stg[lr1 * 132 + lc + 1] = v3;
            }
        }
        __syncthreads();
        float* gdst = (MODE == 1) ? d_h_lin : outp;
        for (int o4 = tid; o4 < 4096; o4 += 128) {
            uint32_t r = o4 >> 5, w4 = o4 & 31;
            *(uint4*)(gdst + (size_t)(m0 + r) * FOUT + n0 + w4 * 4u) =
                *(uint4*)(stg + r * 132u + w4 * 4u);
        }
    }
}

// ---------------- launch -----------------------------------------------------
extern "C" void kernel_launch(void* const* d_in, const int* in_sizes, int n_in,
                              void* d_out, int out_size)
{
    const float* x   = (const float*)d_in[0];
    const int*   adj = (const int*)  d_in[1];
    const float* W   = (const float*)d_in[2];
    const float* a   = (const float*)d_in[3];
    const float* fcw = (const float*)d_in[4];
    const float* fcb = (const float*)d_in[5];
    float* out = (float*)d_out;

    const int frag_sm = 128 * FRAG_PAD * 4;          // 69632

    cudaFuncSetAttribute(k_tc<1>, cudaFuncAttributeMaxDynamicSharedMemorySize, SM_BYTES);
    cudaFuncSetAttribute(k_tc<2>, cudaFuncAttributeMaxDynamicSharedMemorySize, SM_BYTES);
    cudaFuncSetAttribute(k_tc<3>, cudaFuncAttributeMaxDynamicSharedMemorySize, SM_BYTES);
    cudaFuncSetAttribute(k_cvt_x, cudaFuncAttributeMaxDynamicSharedMemorySize, frag_sm);
    cudaFuncSetAttribute(k_att,   cudaFuncAttributeMaxDynamicSharedMemorySize, frag_sm);
    cudaFuncSetAttribute(k_trB,   cudaFuncAttributeMaxDynamicSharedMemorySize, 131072);

    // conversions to fragment-major tf32
    k_cvt_x  <<<MTOT / 16, 256, frag_sm>>>(x);
    k_cvt_wt <<<(FIN * FOUT) / 256, 256>>>(W);
    k_cvt_fcw<<<(FOUT * 2 * FOUT) / 256, 256>>>(fcw);

    // 1) h = x @ W  (writes h A-frag + h linear)
    k_tc<1><<<dim3(FOUT / 128, MTOT / 128), 128, SM_BYTES>>>(nullptr, nullptr);
    // 1b) h^T per batch (B-frag)
    k_trB<<<dim3(FOUT / 32, BB), 256, 131072>>>();
    // 2) f1, f2
    k_f12<<<(MTOT * 32) / 256, 256>>>(a);
    // 3) attention numerators (A-frag) + inverse row sums
    k_att<<<MTOT / 16, 512, frag_sm>>>(adj);
    // 4) agg = softmax(att) @ h
    k_tc<2><<<dim3(FOUT / 128, NN / 128, BB), 128, SM_BYTES>>>(nullptr, nullptr);
    // 5) out = elu([agg, h] @ fc_w^T + fc_b)
    k_tc<3><<<dim3(FOUT / 128, MTOT / 128), 128, SM_BYTES>>>(fcb, out);
}

// round 14
// speedup vs baseline: 1.0421x; 1.0040x over previous
#include <cuda_runtime.h>
#include <math.h>
#include <stdint.h>

#define ALPHA_SLOPE 0.2f
#define NEG_INF_F   -9000000000000000.0f

#define BB    16
#define NN    1024
#define FIN   1024
#define FOUT  512
#define MTOT  (BB*NN)        // 16384

// ---------------- scratch: fragment-major tf32 buffers ----------------------
// A-frag (m16n8k8 A): per 16m x 8k block, 128 floats: idx = t*4 + kq*2 + mh,
//   t=(m&7)*4+(k&3), kq=(k>>2)&1, mh=(m>>3)&1
// B-frag (n-major [n][k]): per 8n x 8k block, 64 floats: idx = t*2 + kq,
//   t=(n&7)*4+(k&3), kq=(k>>2)&1
__device__ float d_x_af  [(size_t)MTOT * FIN];         // 64MB
__device__ float d_wt_bf [(size_t)FOUT * FIN];         // 2MB  (W^T as B-frag)
__device__ float d_fcw_bf[(size_t)FOUT * 2 * FOUT];    // 2MB
__device__ float d_h_lin [(size_t)MTOT * FOUT];        // 32MB (tf32-rounded, linear)
__device__ float d_h_af  [(size_t)MTOT * FOUT];        // 32MB (A-frag, K=512)
__device__ float d_ht_bf [(size_t)BB * FOUT * NN];     // 32MB (h^T B-frag per batch)
__device__ float d_att_af[(size_t)MTOT * NN];          // 64MB (A-frag per batch)
__device__ float d_agg_af[(size_t)MTOT * FOUT];        // 32MB (A-frag, K=512)
__device__ float d_f1 [MTOT];
__device__ float d_f2 [MTOT];
__device__ float d_inv[MTOT];

// ---------------- helpers ----------------------------------------------------
__device__ __forceinline__ uint32_t smem_u32(const void* p) {
    uint32_t a;
    asm("{ .reg .u64 t; cvta.to.shared.u64 t, %1; cvt.u32.u64 %0, t; }" : "=r"(a) : "l"(p));
    return a;
}
__device__ __forceinline__ void cp16(uint32_t s, const void* g) {
    asm volatile("cp.async.cg.shared.global [%0], [%1], 16;" :: "r"(s), "l"(g));
}
__device__ __forceinline__ void lds128(uint32_t* r, uint32_t a) {
    asm volatile("ld.shared.v4.b32 {%0,%1,%2,%3}, [%4];"
        : "=r"(r[0]), "=r"(r[1]), "=r"(r[2]), "=r"(r[3]) : "r"(a));
}
__device__ __forceinline__ void lds64(uint32_t* r, uint32_t a) {
    asm volatile("ld.shared.v2.b32 {%0,%1}, [%2];"
        : "=r"(r[0]), "=r"(r[1]) : "r"(a));
}
__device__ __forceinline__ void mmatf32(float* c, const uint32_t* a, const uint32_t* b) {
    asm volatile("mma.sync.aligned.m16n8k8.row.col.f32.tf32.tf32.f32 "
        "{%0,%1,%2,%3}, {%4,%5,%6,%7}, {%8,%9}, {%0,%1,%2,%3};"
        : "+f"(c[0]), "+f"(c[1]), "+f"(c[2]), "+f"(c[3])
        : "r"(a[0]), "r"(a[1]), "r"(a[2]), "r"(a[3]), "r"(b[0]), "r"(b[1]));
}
__device__ __forceinline__ uint32_t tf32b(float x) {
    uint32_t u;
    asm("cvt.rna.tf32.f32 %0, %1;" : "=r"(u) : "f"(x));
    return u;
}
__device__ __forceinline__ uint32_t afrag_off(uint32_t m, uint32_t k, uint32_t KB8) {
    return ((m >> 4) * KB8 + (k >> 3)) * 128u
         + ((m & 7) * 4 + (k & 3)) * 4u + ((k >> 2) & 1) * 2u + ((m >> 3) & 1);
}
__device__ __forceinline__ uint32_t bfrag_off(uint32_t n, uint32_t k, uint32_t KB8) {
    return ((n >> 3) * KB8 + (k >> 3)) * 64u
         + ((n & 7) * 4 + (k & 3)) * 2u + ((k >> 2) & 1);
}

// ---------------- conversion kernels (max parallelism, scattered) ------------
__global__ void k_cvt_x(const float* __restrict__ x)
{
    uint32_t i = blockIdx.x * 256 + threadIdx.x;     // 16.8M
    uint32_t m = i >> 10, k = i & 1023;
    ((uint32_t*)d_x_af)[afrag_off(m, k, 128)] = tf32b(x[i]);
}
__global__ void k_cvt_wt(const float* __restrict__ W)    // W[1024][512] -> B-frag [n][k]
{
    uint32_t i = blockIdx.x * 256 + threadIdx.x;
    uint32_t n = i & 511, k = i >> 9;
    ((uint32_t*)d_wt_bf)[bfrag_off(n, k, 128)] = tf32b(W[i]);
}
__global__ void k_cvt_fcw(const float* __restrict__ FCW) // fcw[512][1024] -> B-frag
{
    uint32_t i = blockIdx.x * 256 + threadIdx.x;
    uint32_t n = i >> 10, k = i & 1023;
    ((uint32_t*)d_fcw_bf)[bfrag_off(n, k, 128)] = tf32b(FCW[i]);
}

// ---------------- h -> h^T B-frag (per batch) ---------------------------------
__global__ void k_trB()
{
    uint32_t i = blockIdx.x * 256 + threadIdx.x;     // 8.4M, f fastest
    uint32_t mg = i >> 9, f = i & 511;
    uint32_t b = mg >> 10, ml = mg & 1023;
    ((uint32_t*)d_ht_bf)[b * (FOUT * NN) + bfrag_off(f, ml, 128)] =
        ((const uint32_t*)d_h_lin)[i];
}

// ---------------- f1/f2 ------------------------------------------------------
__global__ void k_f12(const float* __restrict__ a)
{
    int row  = (blockIdx.x * blockDim.x + threadIdx.x) >> 5;
    int lane = threadIdx.x & 31;
    if (row >= MTOT) return;
    const float* hr = d_h_lin + (size_t)row * FOUT;
    float s1 = 0.f, s2 = 0.f;
    for (int k = lane; k < FOUT; k += 32) {
        float hv = hr[k];
        s1 = fmaf(hv, a[k], s1);
        s2 = fmaf(hv, a[FOUT + k], s2);
    }
    #pragma unroll
    for (int o = 16; o; o >>= 1) {
        s1 += __shfl_xor_sync(0xffffffffu, s1, o);
        s2 += __shfl_xor_sync(0xffffffffu, s2, o);
    }
    if (lane == 0) { d_f1[row] = s1; d_f2[row] = s2; }
}

// ---------------- attention (one block per row) -------------------------------
__global__ void k_att(const int* __restrict__ adj)
{
    const int row  = blockIdx.x;
    const int b    = row >> 10;
    const uint32_t iloc = row & 1023;
    const int tid  = threadIdx.x;

    __shared__ float sh[NN];
    __shared__ float red[256];

    const float f1i = d_f1[row];
    const int*   arow = adj + (size_t)row * NN;
    const float* f2b  = d_f2 + b * NN;

    float lmax = -INFINITY;
    for (int j = tid; j < NN; j += 256) {
        float e = f1i + f2b[j];
        e = e > 0.f ? e : ALPHA_SLOPE * e;
        e = (arow[j] > 0) ? e : NEG_INF_F;
        sh[j] = e;
        lmax = fmaxf(lmax, e);
    }
    red[tid] = lmax;
    __syncthreads();
    for (int s = 128; s; s >>= 1) {
        if (tid < s) red[tid] = fmaxf(red[tid], red[tid + s]);
        __syncthreads();
    }
    const float m = red[0];
    __syncthreads();

    float lsum = 0.f;
    uint32_t* pA = (uint32_t*)d_att_af + (uint32_t)b * (NN * NN);
    for (int j = tid; j < NN; j += 256) {
        float p = __expf(sh[j] - m);
        pA[afrag_off(iloc, (uint32_t)j, 128)] = tf32b(p);
        lsum += p;
    }
    red[tid] = lsum;
    __syncthreads();
    for (int s = 128; s; s >>= 1) {
        if (tid < s) red[tid] += red[tid + s];
        __syncthreads();
    }
    if (tid == 0) d_inv[row] = 1.f / red[0];
}

// ---------------- tf32 mma GEMM: 128x128 tile, 4 warps of 64x64, BK=32 -------
// 2 stages x 32KB = 64KB smem -> 3 CTAs/SM; launch_bounds(128,3) caps regs ~168
#define A_TILE_B 16384
#define STAGE_B  32768
#define NSTAGE   2
#define SM_BYTES (NSTAGE * STAGE_B)    // 65536 -> 3 CTAs/SM

template<int MODE>
__global__ __launch_bounds__(128, 3)
void k_tc(const float* __restrict__ fcb, float* __restrict__ outp)
{
    extern __shared__ char smem[];
    const uint32_t sb = smem_u32(smem);
    const int tid = threadIdx.x;
    const int wid = tid >> 5, lane = tid & 31;
    const int wm = wid & 1, wn = wid >> 1;       // 2 x 2 warp grid; warp tile 64m x 64n

    const int n0 = blockIdx.x * 128;
    const int m0 = blockIdx.y * 128;             // local row for MODE 2, global else
    const int b  = (MODE == 2) ? blockIdx.z : (m0 >> 10);

    float acc[4][8][4] = {};
    const int NIT = 32;                          // K = 1024, BK = 32

    const float *Ap1, *Ap2, *Bp;
    uint32_t KA8;
    if (MODE == 1) {
        Ap1 = d_x_af;  Ap2 = Ap1; Bp = d_wt_bf;  KA8 = 128;
    } else if (MODE == 2) {
        Ap1 = d_att_af + (uint32_t)b * (NN * NN); Ap2 = Ap1;
        Bp  = d_ht_bf  + (uint32_t)b * (FOUT * NN); KA8 = 128;
    } else {
        Ap1 = d_agg_af; Ap2 = d_h_af; Bp = d_fcw_bf; KA8 = 64;
    }

    uint32_t a_base0, a_dst0, b_base0, b_dst0;
    {
        uint32_t blk = (uint32_t)tid >> 5, w = (uint32_t)tid & 31;
        uint32_t mb = blk >> 2, kb = blk & 3;
        a_base0 = (((uint32_t)(m0 >> 4) + mb) * KA8 + kb) * 128u + w * 4u;
        a_dst0  = blk * 512u + w * 16u;
        blk = (uint32_t)tid >> 4; w = (uint32_t)tid & 15;
        uint32_t nb = blk >> 2, kbb = blk & 3;
        b_base0 = (((uint32_t)(n0 >> 3) + nb) * 128u + kbb) * 64u + w * 4u;
        b_dst0  = A_TILE_B + blk * 256u + w * 16u;
    }
    const uint32_t a_bstride = KA8 * 128u;

    auto issue = [&](int c) {
        const uint32_t st = sb + (c & 1) * STAGE_B;
        const float* Ap = (MODE == 3 && c >= 16) ? Ap2 : Ap1;
        const uint32_t ca = (MODE == 3) ? (uint32_t)(c & 15) * 512u : (uint32_t)c * 512u;
        const uint32_t cb = (uint32_t)c * 256u;
        #pragma unroll
        for (uint32_t j = 0; j < 8; j++)
            cp16(st + a_dst0 + j * 2048u, Ap + a_base0 + j * a_bstride + ca);
        #pragma unroll
        for (uint32_t j = 0; j < 8; j++)
            cp16(st + b_dst0 + j * 2048u, Bp + b_base0 + j * 16384u + cb);
        asm volatile("cp.async.commit_group;" ::: "memory");
    };

    const uint32_t a_lds = (uint32_t)lane * 16u;
    const uint32_t b_lds = A_TILE_B + (uint32_t)lane * 8u;

    issue(0);
    #pragma unroll 1
    for (int c = 0; c < NIT; c++) {
        asm volatile("cp.async.wait_group 0;" ::: "memory");
        __syncthreads();                 // stage c readable; other buffer free
        if (c + 1 < NIT) issue(c + 1);

        const uint32_t base = sb + (c & 1) * STAGE_B;
        #pragma unroll
        for (int ks = 0; ks < 4; ks++) {
            uint32_t bf[8][2];
            #pragma unroll
            for (int nt = 0; nt < 8; nt++)
                lds64(bf[nt], base + b_lds + ((wn * 8 + nt) * 4 + ks) * 256u);
            #pragma unroll
            for (int mt = 0; mt < 4; mt++) {
                uint32_t af[4];
                lds128(af, base + a_lds + ((wm * 4 + mt) * 4 + ks) * 512u);
                #pragma unroll
                for (int nt = 0; nt < 8; nt++) mmatf32(acc[mt][nt], af, bf[nt]);
            }
        }
    }

    __syncthreads();

    // ---------------- epilogue: smem-staged, bulk-linear global writes -------
    const int g = lane >> 2, tig = lane & 3;
    float* stg = (float*)smem;

    if (MODE == 1 || MODE == 2) {
        // phase A: A-frag tile stage (8 mg x 16 kb x 128 = 65536 B)
        #pragma unroll
        for (int mt = 0; mt < 4; mt++) {
            const int lr0 = wm * 64 + mt * 16 + g;
            float s0 = 1.f, s1 = 1.f;
            if (MODE == 2) {
                s0 = d_inv[b * NN + m0 + lr0];
                s1 = d_inv[b * NN + m0 + lr0 + 8];
            }
            #pragma unroll
            for (int nt = 0; nt < 8; nt++) {
                float* c = acc[mt][nt];
                const uint32_t kb_l = wn * 8 + nt;
                const uint32_t t0 = g * 4 + ((tig * 2) & 3);
                const uint32_t basei = ((uint32_t)(wm * 4 + mt) * 16 + kb_l) * 128u
                                     + (uint32_t)(tig >> 1) * 2u;
                stg[basei + t0 * 4 + 0]       = __uint_as_float(tf32b(c[0] * s0));
                stg[basei + (t0 + 1) * 4 + 0] = __uint_as_float(tf32b(c[1] * s0));
                stg[basei + t0 * 4 + 1]       = __uint_as_float(tf32b(c[2] * s1));
                stg[basei + (t0 + 1) * 4 + 1] = __uint_as_float(tf32b(c[3] * s1));
            }
        }
        __syncthreads();
        const uint32_t MGb = (MODE == 2) ? (uint32_t)(b * NN + m0) >> 4 : (uint32_t)m0 >> 4;
        uint4* gdst = (uint4*)((MODE == 1) ? (uint32_t*)d_h_af : (uint32_t*)d_agg_af);
        for (int o4 = tid; o4 < 4096; o4 += 128) {
            uint32_t mg_l = o4 >> 9, rest = o4 & 511;
            gdst[(size_t)(MGb + mg_l) * 2048u + ((uint32_t)n0 >> 3) * 32u + rest] =
                *(uint4*)(stg + (size_t)o4 * 4u);
        }
        __syncthreads();
    }

    if (MODE == 1 || MODE == 3) {
        // phase B: linear tile in 2 halves of 64 rows (64*132*4 = 33792 B fits)
        #pragma unroll 1
        for (int half = 0; half < 2; half++) {
            if (wm == half) {
                #pragma unroll
                for (int mt = 0; mt < 4; mt++) {
                    const int sr0 = mt * 16 + g;          // 0..63 local
                    const int sr1 = sr0 + 8;
                    #pragma unroll
                    for (int nt = 0; nt < 8; nt++) {
                        float* c = acc[mt][nt];
                        const int lc = wn * 64 + nt * 8 + tig * 2;
                        float v0, v1, v2, v3;
                        if (MODE == 1) {
                            v0 = __uint_as_float(tf32b(c[0]));
                            v1 = __uint_as_float(tf32b(c[1]));
                            v2 = __uint_as_float(tf32b(c[2]));
                            v3 = __uint_as_float(tf32b(c[3]));
                        } else {
                            float b0 = fcb[n0 + lc], b1 = fcb[n0 + lc + 1];
                            v0 = c[0] + b0; v0 = v0 > 0.f ? v0 : expm1f(v0);
                            v1 = c[1] + b1; v1 = v1 > 0.f ? v1 : expm1f(v1);
                            v2 = c[2] + b0; v2 = v2 > 0.f ? v2 : expm1f(v2);
                            v3 = c[3] + b1; v3 = v3 > 0.f ? v3 : expm1f(v3);
                        }
                        stg[sr0 * 132 + lc] = v0; stg[sr0 * 132 + lc + 1] = v1;
                        stg[sr1 * 132 + lc] = v2; stg[sr1 * 132 + lc + 1] = v3;
                    }
                }
            }
            __syncthreads();
            float* gdst = (MODE == 1) ? d_h_lin : outp;
            for (int o4 = tid; o4 < 2048; o4 += 128) {
                uint32_t r = o4 >> 5, w4 = o4 & 31;
                *(uint4*)(gdst + (size_t)(m0 + half * 64 + r) * FOUT + n0 + w4 * 4u) =
                    *(uint4*)(stg + r * 132u + w4 * 4u);
            }
            __syncthreads();
        }
    }
}

// ---------------- launch -----------------------------------------------------
extern "C" void kernel_launch(void* const* d_in, const int* in_sizes, int n_in,
                              void* d_out, int out_size)
{
    const float* x   = (const float*)d_in[0];
    const int*   adj = (const int*)  d_in[1];
    const float* W   = (const float*)d_in[2];
    const float* a   = (const float*)d_in[3];
    const float* fcw = (const float*)d_in[4];
    const float* fcb = (const float*)d_in[5];
    float* out = (float*)d_out;

    cudaFuncSetAttribute(k_tc<1>, cudaFuncAttributeMaxDynamicSharedMemorySize, SM_BYTES);
    cudaFuncSetAttribute(k_tc<2>, cudaFuncAttributeMaxDynamicSharedMemorySize, SM_BYTES);
    cudaFuncSetAttribute(k_tc<3>, cudaFuncAttributeMaxDynamicSharedMemorySize, SM_BYTES);

    // conversions to fragment-major tf32
    k_cvt_x  <<<(MTOT * FIN) / 256, 256>>>(x);
    k_cvt_wt <<<(FIN * FOUT) / 256, 256>>>(W);
    k_cvt_fcw<<<(FOUT * 2 * FOUT) / 256, 256>>>(fcw);

    // 1) h = x @ W  (writes h A-frag + h linear)
    k_tc<1><<<dim3(FOUT / 128, MTOT / 128), 128, SM_BYTES>>>(nullptr, nullptr);
    // 1b) h^T per batch (B-frag)
    k_trB<<<(MTOT * FOUT) / 256, 256>>>();
    // 2) f1, f2
    k_f12<<<(MTOT * 32) / 256, 256>>>(a);
    // 3) attention numerators (A-frag) + inverse row sums
    k_att<<<MTOT, 256>>>(adj);
    // 4) agg = softmax(att) @ h
    k_tc<2><<<dim3(FOUT / 128, NN / 128, BB), 128, SM_BYTES>>>(nullptr, nullptr);
    // 5) out = elu([agg, h] @ fc_w^T + fc_b)
    k_tc<3><<<dim3(FOUT / 128, MTOT / 128), 128, SM_BYTES>>>(fcb, out);
}

// round 15
// speedup vs baseline: 1.1073x; 1.0626x over previous
#include <cuda_runtime.h>
#include <math.h>
#include <stdint.h>

#define ALPHA_SLOPE 0.2f
#define NEG_INF_F   -9000000000000000.0f

#define BB    16
#define NN    1024
#define FIN   1024
#define FOUT  512
#define MTOT  (BB*NN)        // 16384

// ---------------- scratch: fragment-major tf32 buffers ----------------------
__device__ float d_x_af  [(size_t)MTOT * FIN];         // 64MB
__device__ float d_wt_bf [(size_t)FOUT * FIN];         // 2MB  (W^T as B-frag)
__device__ float d_fcw_bf[(size_t)FOUT * 2 * FOUT];    // 2MB
__device__ float d_h_lin [(size_t)MTOT * FOUT];        // 32MB (tf32-rounded, linear)
__device__ float d_h_af  [(size_t)MTOT * FOUT];        // 32MB (A-frag, K=512)
__device__ float d_ht_bf [(size_t)BB * FOUT * NN];     // 32MB (h^T B-frag per batch)
__device__ float d_att_af[(size_t)MTOT * NN];          // 64MB (A-frag per batch)
__device__ float d_agg_af[(size_t)MTOT * FOUT];        // 32MB (A-frag, K=512)
__device__ float d_f1 [MTOT];
__device__ float d_f2 [MTOT];
__device__ float d_inv[MTOT];

// ---------------- helpers ----------------------------------------------------
__device__ __forceinline__ uint32_t smem_u32(const void* p) {
    uint32_t a;
    asm("{ .reg .u64 t; cvta.to.shared.u64 t, %1; cvt.u32.u64 %0, t; }" : "=r"(a) : "l"(p));
    return a;
}
__device__ __forceinline__ void cp16(uint32_t s, const void* g) {
    asm volatile("cp.async.cg.shared.global [%0], [%1], 16;" :: "r"(s), "l"(g));
}
__device__ __forceinline__ void lds128(uint32_t* r, uint32_t a) {
    asm volatile("ld.shared.v4.b32 {%0,%1,%2,%3}, [%4];"
        : "=r"(r[0]), "=r"(r[1]), "=r"(r[2]), "=r"(r[3]) : "r"(a));
}
__device__ __forceinline__ void lds64(uint32_t* r, uint32_t a) {
    asm volatile("ld.shared.v2.b32 {%0,%1}, [%2];"
        : "=r"(r[0]), "=r"(r[1]) : "r"(a));
}
__device__ __forceinline__ void mmatf32(float* c, const uint32_t* a, const uint32_t* b) {
    asm volatile("mma.sync.aligned.m16n8k8.row.col.f32.tf32.tf32.f32 "
        "{%0,%1,%2,%3}, {%4,%5,%6,%7}, {%8,%9}, {%0,%1,%2,%3};"
        : "+f"(c[0]), "+f"(c[1]), "+f"(c[2]), "+f"(c[3])
        : "r"(a[0]), "r"(a[1]), "r"(a[2]), "r"(a[3]), "r"(b[0]), "r"(b[1]));
}
__device__ __forceinline__ uint32_t tf32b(float x) {
    uint32_t u;
    asm("cvt.rna.tf32.f32 %0, %1;" : "=r"(u) : "f"(x));
    return u;
}
__device__ __forceinline__ uint32_t afrag_off(uint32_t m, uint32_t k, uint32_t KB8) {
    return ((m >> 4) * KB8 + (k >> 3)) * 128u
         + ((m & 7) * 4 + (k & 3)) * 4u + ((k >> 2) & 1) * 2u + ((m >> 3) & 1);
}
__device__ __forceinline__ uint32_t bfrag_off(uint32_t n, uint32_t k, uint32_t KB8) {
    return ((n >> 3) * KB8 + (k >> 3)) * 64u
         + ((n & 7) * 4 + (k & 3)) * 2u + ((k >> 2) & 1);
}

// ---------------- conversion kernels (max parallelism, scattered) ------------
__global__ void k_cvt_x(const float* __restrict__ x)
{
    uint32_t i = blockIdx.x * 256 + threadIdx.x;     // 16.8M
    uint32_t m = i >> 10, k = i & 1023;
    ((uint32_t*)d_x_af)[afrag_off(m, k, 128)] = tf32b(x[i]);
}
__global__ void k_cvt_wt(const float* __restrict__ W)    // W[1024][512] -> B-frag [n][k]
{
    uint32_t i = blockIdx.x * 256 + threadIdx.x;
    uint32_t n = i & 511, k = i >> 9;
    ((uint32_t*)d_wt_bf)[bfrag_off(n, k, 128)] = tf32b(W[i]);
}
__global__ void k_cvt_fcw(const float* __restrict__ FCW) // fcw[512][1024] -> B-frag
{
    uint32_t i = blockIdx.x * 256 + threadIdx.x;
    uint32_t n = i >> 10, k = i & 1023;
    ((uint32_t*)d_fcw_bf)[bfrag_off(n, k, 128)] = tf32b(FCW[i]);
}

// ---------------- h -> h^T B-frag (per batch) ---------------------------------
__global__ void k_trB()
{
    uint32_t i = blockIdx.x * 256 + threadIdx.x;     // 8.4M, f fastest
    uint32_t mg = i >> 9, f = i & 511;
    uint32_t b = mg >> 10, ml = mg & 1023;
    ((uint32_t*)d_ht_bf)[b * (FOUT * NN) + bfrag_off(f, ml, 128)] =
        ((const uint32_t*)d_h_lin)[i];
}

// ---------------- f1/f2 ------------------------------------------------------
__global__ void k_f12(const float* __restrict__ a)
{
    int row  = (blockIdx.x * blockDim.x + threadIdx.x) >> 5;
    int lane = threadIdx.x & 31;
    if (row >= MTOT) return;
    const float* hr = d_h_lin + (size_t)row * FOUT;
    float s1 = 0.f, s2 = 0.f;
    for (int k = lane; k < FOUT; k += 32) {
        float hv = hr[k];
        s1 = fmaf(hv, a[k], s1);
        s2 = fmaf(hv, a[FOUT + k], s2);
    }
    #pragma unroll
    for (int o = 16; o; o >>= 1) {
        s1 += __shfl_xor_sync(0xffffffffu, s1, o);
        s2 += __shfl_xor_sync(0xffffffffu, s2, o);
    }
    if (lane == 0) { d_f1[row] = s1; d_f2[row] = s2; }
}

// ---------------- attention (one block per row) -------------------------------
__global__ void k_att(const int* __restrict__ adj)
{
    const int row  = blockIdx.x;
    const int b    = row >> 10;
    const uint32_t iloc = row & 1023;
    const int tid  = threadIdx.x;

    __shared__ float sh[NN];
    __shared__ float red[256];

    const float f1i = d_f1[row];
    const int*   arow = adj + (size_t)row * NN;
    const float* f2b  = d_f2 + b * NN;

    float lmax = -INFINITY;
    for (int j = tid; j < NN; j += 256) {
        float e = f1i + f2b[j];
        e = e > 0.f ? e : ALPHA_SLOPE * e;
        e = (arow[j] > 0) ? e : NEG_INF_F;
        sh[j] = e;
        lmax = fmaxf(lmax, e);
    }
    red[tid] = lmax;
    __syncthreads();
    for (int s = 128; s; s >>= 1) {
        if (tid < s) red[tid] = fmaxf(red[tid], red[tid + s]);
        __syncthreads();
    }
    const float m = red[0];
    __syncthreads();

    float lsum = 0.f;
    uint32_t* pA = (uint32_t*)d_att_af + (uint32_t)b * (NN * NN);
    for (int j = tid; j < NN; j += 256) {
        float p = __expf(sh[j] - m);
        pA[afrag_off(iloc, (uint32_t)j, 128)] = tf32b(p);
        lsum += p;
    }
    red[tid] = lsum;
    __syncthreads();
    for (int s = 128; s; s >>= 1) {
        if (tid < s) red[tid] += red[tid + s];
        __syncthreads();
    }
    if (tid == 0) d_inv[row] = 1.f / red[0];
}

// ---------------- tf32 mma GEMM: 128x128 tile, 4 warps of 64x64, BK=32 -------
// 3 stages x 32KB = 96KB smem -> 2 CTAs/SM; regs ~210 (launch_bounds(128,2))
#define A_TILE_B 16384
#define STAGE_B  32768
#define NSTAGE   3
#define SM_BYTES (NSTAGE * STAGE_B)    // 98304 -> 2 CTAs/SM

template<int MODE>
__global__ __launch_bounds__(128, 2)
void k_tc(const float* __restrict__ fcb, float* __restrict__ outp)
{
    extern __shared__ char smem[];
    const uint32_t sb = smem_u32(smem);
    const int tid = threadIdx.x;
    const int wid = tid >> 5, lane = tid & 31;
    const int wm = wid & 1, wn = wid >> 1;       // 2 x 2 warp grid; warp tile 64m x 64n

    const int n0 = blockIdx.x * 128;
    const int m0 = blockIdx.y * 128;             // local row for MODE 2, global else
    const int b  = (MODE == 2) ? blockIdx.z : (m0 >> 10);

    float acc[4][8][4] = {};
    const int NIT = 32;                          // K = 1024, BK = 32

    const float *Ap1, *Ap2, *Bp;
    uint32_t KA8;
    if (MODE == 1) {
        Ap1 = d_x_af;  Ap2 = Ap1; Bp = d_wt_bf;  KA8 = 128;
    } else if (MODE == 2) {
        Ap1 = d_att_af + (uint32_t)b * (NN * NN); Ap2 = Ap1;
        Bp  = d_ht_bf  + (uint32_t)b * (FOUT * NN); KA8 = 128;
    } else {
        Ap1 = d_agg_af; Ap2 = d_h_af; Bp = d_fcw_bf; KA8 = 64;
    }

    uint32_t a_base0, a_dst0, b_base0, b_dst0;
    {
        uint32_t blk = (uint32_t)tid >> 5, w = (uint32_t)tid & 31;
        uint32_t mb = blk >> 2, kb = blk & 3;
        a_base0 = (((uint32_t)(m0 >> 4) + mb) * KA8 + kb) * 128u + w * 4u;
        a_dst0  = blk * 512u + w * 16u;
        blk = (uint32_t)tid >> 4; w = (uint32_t)tid & 15;
        uint32_t nb = blk >> 2, kbb = blk & 3;
        b_base0 = (((uint32_t)(n0 >> 3) + nb) * 128u + kbb) * 64u + w * 4u;
        b_dst0  = A_TILE_B + blk * 256u + w * 16u;
    }
    const uint32_t a_bstride = KA8 * 128u;

    auto issue = [&](int c) {
        const uint32_t st = sb + (c % NSTAGE) * STAGE_B;
        const float* Ap = (MODE == 3 && c >= 16) ? Ap2 : Ap1;
        const uint32_t ca = (MODE == 3) ? (uint32_t)(c & 15) * 512u : (uint32_t)c * 512u;
        const uint32_t cb = (uint32_t)c * 256u;
        #pragma unroll
        for (uint32_t j = 0; j < 8; j++)
            cp16(st + a_dst0 + j * 2048u, Ap + a_base0 + j * a_bstride + ca);
        #pragma unroll
        for (uint32_t j = 0; j < 8; j++)
            cp16(st + b_dst0 + j * 2048u, Bp + b_base0 + j * 16384u + cb);
        asm volatile("cp.async.commit_group;" ::: "memory");
    };

    const uint32_t a_lds = (uint32_t)lane * 16u;
    const uint32_t b_lds = A_TILE_B + (uint32_t)lane * 8u;

    issue(0);
    issue(1);
    #pragma unroll 1
    for (int c = 0; c < NIT; c++) {
        if (c == NIT - 1) asm volatile("cp.async.wait_group 0;" ::: "memory");
        else              asm volatile("cp.async.wait_group 1;" ::: "memory");
        __syncthreads();
        if (c + 2 < NIT) issue(c + 2);

        const uint32_t base = sb + (c % NSTAGE) * STAGE_B;
        #pragma unroll
        for (int ks = 0; ks < 4; ks++) {
            uint32_t bf[8][2];
            #pragma unroll
            for (int nt = 0; nt < 8; nt++)
                lds64(bf[nt], base + b_lds + ((wn * 8 + nt) * 4 + ks) * 256u);
            #pragma unroll
            for (int mt = 0; mt < 4; mt++) {
                uint32_t af[4];
                lds128(af, base + a_lds + ((wm * 4 + mt) * 4 + ks) * 512u);
                #pragma unroll
                for (int nt = 0; nt < 8; nt++) mmatf32(acc[mt][nt], af, bf[nt]);
            }
        }
    }

    __syncthreads();

    // ---------------- epilogue: smem-staged, bulk-linear global writes -------
    const int g = lane >> 2, tig = lane & 3;
    float* stg = (float*)smem;

    if (MODE == 1 || MODE == 2) {
        // phase A: A-frag tile stage (8 mg x 16 kb x 128 = 65536 B)
        #pragma unroll
        for (int mt = 0; mt < 4; mt++) {
            const int lr0 = wm * 64 + mt * 16 + g;
            float s0 = 1.f, s1 = 1.f;
            if (MODE == 2) {
                s0 = d_inv[b * NN + m0 + lr0];
                s1 = d_inv[b * NN + m0 + lr0 + 8];
            }
            #pragma unroll
            for (int nt = 0; nt < 8; nt++) {
                float* c = acc[mt][nt];
                const uint32_t kb_l = wn * 8 + nt;
                const uint32_t t0 = g * 4 + ((tig * 2) & 3);
                const uint32_t basei = ((uint32_t)(wm * 4 + mt) * 16 + kb_l) * 128u
                                     + (uint32_t)(tig >> 1) * 2u;
                stg[basei + t0 * 4 + 0]       = __uint_as_float(tf32b(c[0] * s0));
                stg[basei + (t0 + 1) * 4 + 0] = __uint_as_float(tf32b(c[1] * s0));
                stg[basei + t0 * 4 + 1]       = __uint_as_float(tf32b(c[2] * s1));
                stg[basei + (t0 + 1) * 4 + 1] = __uint_as_float(tf32b(c[3] * s1));
            }
        }
        __syncthreads();
        const uint32_t MGb = (MODE == 2) ? (uint32_t)(b * NN + m0) >> 4 : (uint32_t)m0 >> 4;
        uint4* gdst = (uint4*)((MODE == 1) ? (uint32_t*)d_h_af : (uint32_t*)d_agg_af);
        for (int o4 = tid; o4 < 4096; o4 += 128) {
            uint32_t mg_l = o4 >> 9, rest = o4 & 511;
            gdst[(size_t)(MGb + mg_l) * 2048u + ((uint32_t)n0 >> 3) * 32u + rest] =
                *(uint4*)(stg + (size_t)o4 * 4u);
        }
        __syncthreads();
    }

    if (MODE == 1 || MODE == 3) {
        // phase B: linear 128x128 tile (row pad 132; 67584 B <= 98304 B)
        #pragma unroll
        for (int mt = 0; mt < 4; mt++) {
            const int lr0 = wm * 64 + mt * 16 + g;
            const int lr1 = lr0 + 8;
            #pragma unroll
            for (int nt = 0; nt < 8; nt++) {
                float* c = acc[mt][nt];
                const int lc = wn * 64 + nt * 8 + tig * 2;
                float v0, v1, v2, v3;
                if (MODE == 1) {
                    v0 = __uint_as_float(tf32b(c[0]));
                    v1 = __uint_as_float(tf32b(c[1]));
                    v2 = __uint_as_float(tf32b(c[2]));
                    v3 = __uint_as_float(tf32b(c[3]));
                } else {
                    float b0 = fcb[n0 + lc], b1 = fcb[n0 + lc + 1];
                    v0 = c[0] + b0; v0 = v0 > 0.f ? v0 : expm1f(v0);
                    v1 = c[1] + b1; v1 = v1 > 0.f ? v1 : expm1f(v1);
                    v2 = c[2] + b0; v2 = v2 > 0.f ? v2 : expm1f(v2);
                    v3 = c[3] + b1; v3 = v3 > 0.f ? v3 : expm1f(v3);
                }
                stg[lr0 * 132 + lc] = v0; stg[lr0 * 132 + lc + 1] = v1;
                stg[lr1 * 132 + lc] = v2; stg[lr1 * 132 + lc + 1] = v3;
            }
        }
        __syncthreads();
        float* gdst = (MODE == 1) ? d_h_lin : outp;
        for (int o4 = tid; o4 < 4096; o4 += 128) {
            uint32_t r = o4 >> 5, w4 = o4 & 31;
            *(uint4*)(gdst + (size_t)(m0 + r) * FOUT + n0 + w4 * 4u) =
                *(uint4*)(stg + r * 132u + w4 * 4u);
        }
    }
}

// ---------------- launch -----------------------------------------------------
extern "C" void kernel_launch(void* const* d_in, const int* in_sizes, int n_in,
                              void* d_out, int out_size)
{
    const float* x   = (const float*)d_in[0];
    const int*   adj = (const int*)  d_in[1];
    const float* W   = (const float*)d_in[2];
    const float* a   = (const float*)d_in[3];
    const float* fcw = (const float*)d_in[4];
    const float* fcb = (const float*)d_in[5];
    float* out = (float*)d_out;

    cudaFuncSetAttribute(k_tc<1>, cudaFuncAttributeMaxDynamicSharedMemorySize, SM_BYTES);
    cudaFuncSetAttribute(k_tc<2>, cudaFuncAttributeMaxDynamicSharedMemorySize, SM_BYTES);
    cudaFuncSetAttribute(k_tc<3>, cudaFuncAttributeMaxDynamicSharedMemorySize, SM_BYTES);

    // conversions to fragment-major tf32
    k_cvt_x  <<<(MTOT * FIN) / 256, 256>>>(x);
    k_cvt_wt <<<(FIN * FOUT) / 256, 256>>>(W);
    k_cvt_fcw<<<(FOUT * 2 * FOUT) / 256, 256>>>(fcw);

    // 1) h = x @ W  (writes h A-frag + h linear)
    k_tc<1><<<dim3(FOUT / 128, MTOT / 128), 128, SM_BYTES>>>(nullptr, nullptr);
    // 1b) h^T per batch (B-frag)
    k_trB<<<(MTOT * FOUT) / 256, 256>>>();
    // 2) f1, f2
    k_f12<<<(MTOT * 32) / 256, 256>>>(a);
    // 3) attention numerators (A-frag) + inverse row sums
    k_att<<<MTOT, 256>>>(adj);
    // 4) agg = softmax(att) @ h
    k_tc<2><<<dim3(FOUT / 128, NN / 128, BB), 128, SM_BYTES>>>(nullptr, nullptr);
    // 5) out = elu([agg, h] @ fc_w^T + fc_b)
    k_tc<3><<<dim3(FOUT / 128, MTOT / 128), 128, SM_BYTES>>>(fcb, out);
}

// round 16
// speedup vs baseline: 1.2098x; 1.0926x over previous
#include <cuda_runtime.h>
#include <math.h>
#include <stdint.h>

#define ALPHA_SLOPE 0.2f
#define NEG_INF_F   -9000000000000000.0f

#define BB    16
#define NN    1024
#define FIN   1024
#define FOUT  512
#define MTOT  (BB*NN)        // 16384

// ---------------- scratch: fragment-major tf32 buffers ----------------------
__device__ float d_x_af  [(size_t)MTOT * FIN];         // 64MB
__device__ float d_wt_bf [(size_t)FOUT * FIN];         // 2MB  (W^T as B-frag)
__device__ float d_fcw_bf[(size_t)FOUT * 2 * FOUT];    // 2MB
__device__ float d_h_af  [(size_t)MTOT * FOUT];        // 32MB (A-frag, K=512)
__device__ float d_ht_bf [(size_t)BB * FOUT * NN];     // 32MB (h^T B-frag per batch)
__device__ float d_att_af[(size_t)MTOT * NN];          // 64MB (A-frag per batch)
__device__ float d_agg_af[(size_t)MTOT * FOUT];        // 32MB (A-frag, K=512)
__device__ float d_f1p[4 * MTOT];                      // per-n-tile partials
__device__ float d_f2p[4 * MTOT];
__device__ float d_f1 [MTOT];
__device__ float d_f2 [MTOT];
__device__ float d_inv[MTOT];

// ---------------- helpers ----------------------------------------------------
__device__ __forceinline__ uint32_t smem_u32(const void* p) {
    uint32_t a;
    asm("{ .reg .u64 t; cvta.to.shared.u64 t, %1; cvt.u32.u64 %0, t; }" : "=r"(a) : "l"(p));
    return a;
}
__device__ __forceinline__ void cp16(uint32_t s, const void* g) {
    asm volatile("cp.async.cg.shared.global [%0], [%1], 16;" :: "r"(s), "l"(g));
}
__device__ __forceinline__ void lds128(uint32_t* r, uint32_t a) {
    asm volatile("ld.shared.v4.b32 {%0,%1,%2,%3}, [%4];"
        : "=r"(r[0]), "=r"(r[1]), "=r"(r[2]), "=r"(r[3]) : "r"(a));
}
__device__ __forceinline__ void lds64(uint32_t* r, uint32_t a) {
    asm volatile("ld.shared.v2.b32 {%0,%1}, [%2];"
        : "=r"(r[0]), "=r"(r[1]) : "r"(a));
}
__device__ __forceinline__ void mmatf32(float* c, const uint32_t* a, const uint32_t* b) {
    asm volatile("mma.sync.aligned.m16n8k8.row.col.f32.tf32.tf32.f32 "
        "{%0,%1,%2,%3}, {%4,%5,%6,%7}, {%8,%9}, {%0,%1,%2,%3};"
        : "+f"(c[0]), "+f"(c[1]), "+f"(c[2]), "+f"(c[3])
        : "r"(a[0]), "r"(a[1]), "r"(a[2]), "r"(a[3]), "r"(b[0]), "r"(b[1]));
}
__device__ __forceinline__ uint32_t tf32b(float x) {
    uint32_t u;
    asm("cvt.rna.tf32.f32 %0, %1;" : "=r"(u) : "f"(x));
    return u;
}
__device__ __forceinline__ uint32_t afrag_off(uint32_t m, uint32_t k, uint32_t KB8) {
    return ((m >> 4) * KB8 + (k >> 3)) * 128u
         + ((m & 7) * 4 + (k & 3)) * 4u + ((k >> 2) & 1) * 2u + ((m >> 3) & 1);
}
__device__ __forceinline__ uint32_t bfrag_off(uint32_t n, uint32_t k, uint32_t KB8) {
    return ((n >> 3) * KB8 + (k >> 3)) * 64u
         + ((n & 7) * 4 + (k & 3)) * 2u + ((k >> 2) & 1);
}

// ---------------- conversion kernels (max parallelism, scattered) ------------
__global__ void k_cvt_x(const float* __restrict__ x)
{
    uint32_t i = blockIdx.x * 256 + threadIdx.x;     // 16.8M
    uint32_t m = i >> 10, k = i & 1023;
    ((uint32_t*)d_x_af)[afrag_off(m, k, 128)] = tf32b(x[i]);
}
__global__ void k_cvt_wt(const float* __restrict__ W)    // W[1024][512] -> B-frag [n][k]
{
    uint32_t i = blockIdx.x * 256 + threadIdx.x;
    uint32_t n = i & 511, k = i >> 9;
    ((uint32_t*)d_wt_bf)[bfrag_off(n, k, 128)] = tf32b(W[i]);
}
__global__ void k_cvt_fcw(const float* __restrict__ FCW) // fcw[512][1024] -> B-frag
{
    uint32_t i = blockIdx.x * 256 + threadIdx.x;
    uint32_t n = i >> 10, k = i & 1023;
    ((uint32_t*)d_fcw_bf)[bfrag_off(n, k, 128)] = tf32b(FCW[i]);
}

// ---------------- f1/f2 partial reduction (4 n-tiles -> final) ---------------
__global__ void k_fred()
{
    int r = blockIdx.x * 256 + threadIdx.x;
    d_f1[r] = d_f1p[r] + d_f1p[MTOT + r] + d_f1p[2 * MTOT + r] + d_f1p[3 * MTOT + r];
    d_f2[r] = d_f2p[r] + d_f2p[MTOT + r] + d_f2p[2 * MTOT + r] + d_f2p[3 * MTOT + r];
}

// ---------------- attention (one block per row) -------------------------------
__global__ void k_att(const int* __restrict__ adj)
{
    const int row  = blockIdx.x;
    const int b    = row >> 10;
    const uint32_t iloc = row & 1023;
    const int tid  = threadIdx.x;

    __shared__ float sh[NN];
    __shared__ float red[256];

    const float f1i = d_f1[row];
    const int*   arow = adj + (size_t)row * NN;
    const float* f2b  = d_f2 + b * NN;

    float lmax = -INFINITY;
    for (int j = tid; j < NN; j += 256) {
        float e = f1i + f2b[j];
        e = e > 0.f ? e : ALPHA_SLOPE * e;
        e = (arow[j] > 0) ? e : NEG_INF_F;
        sh[j] = e;
        lmax = fmaxf(lmax, e);
    }
    red[tid] = lmax;
    __syncthreads();
    for (int s = 128; s; s >>= 1) {
        if (tid < s) red[tid] = fmaxf(red[tid], red[tid + s]);
        __syncthreads();
    }
    const float m = red[0];
    __syncthreads();

    float lsum = 0.f;
    uint32_t* pA = (uint32_t*)d_att_af + (uint32_t)b * (NN * NN);
    for (int j = tid; j < NN; j += 256) {
        float p = __expf(sh[j] - m);
        pA[afrag_off(iloc, (uint32_t)j, 128)] = tf32b(p);
        lsum += p;
    }
    red[tid] = lsum;
    __syncthreads();
    for (int s = 128; s; s >>= 1) {
        if (tid < s) red[tid] += red[tid + s];
        __syncthreads();
    }
    if (tid == 0) d_inv[row] = 1.f / red[0];
}

// ---------------- tf32 mma GEMM: 128x128 tile, 4 warps of 64x64, BK=32 -------
// 3 stages x 32KB = 96KB smem -> 2 CTAs/SM; regs ~210 (launch_bounds(128,2))
#define A_TILE_B 16384
#define STAGE_B  32768
#define NSTAGE   3
#define SM_BYTES (NSTAGE * STAGE_B)    // 98304 -> 2 CTAs/SM

template<int MODE>
__global__ __launch_bounds__(128, 2)
void k_tc(const float* __restrict__ fcb, float* __restrict__ outp)
{
    extern __shared__ char smem[];
    const uint32_t sb = smem_u32(smem);
    const int tid = threadIdx.x;
    const int wid = tid >> 5, lane = tid & 31;
    const int wm = wid & 1, wn = wid >> 1;       // 2 x 2 warp grid; warp tile 64m x 64n

    const int n0 = blockIdx.x * 128;
    const int m0 = blockIdx.y * 128;             // local row for MODE 2, global else
    const int b  = (MODE == 2) ? blockIdx.z : (m0 >> 10);

    float acc[4][8][4] = {};
    const int NIT = 32;                          // K = 1024, BK = 32

    const float *Ap1, *Ap2, *Bp;
    uint32_t KA8;
    if (MODE == 1) {
        Ap1 = d_x_af;  Ap2 = Ap1; Bp = d_wt_bf;  KA8 = 128;
    } else if (MODE == 2) {
        Ap1 = d_att_af + (uint32_t)b * (NN * NN); Ap2 = Ap1;
        Bp  = d_ht_bf  + (uint32_t)b * (FOUT * NN); KA8 = 128;
    } else {
        Ap1 = d_agg_af; Ap2 = d_h_af; Bp = d_fcw_bf; KA8 = 64;
    }

    uint32_t a_base0, a_dst0, b_base0, b_dst0;
    {
        uint32_t blk = (uint32_t)tid >> 5, w = (uint32_t)tid & 31;
        uint32_t mb = blk >> 2, kb = blk & 3;
        a_base0 = (((uint32_t)(m0 >> 4) + mb) * KA8 + kb) * 128u + w * 4u;
        a_dst0  = blk * 512u + w * 16u;
        blk = (uint32_t)tid >> 4; w = (uint32_t)tid & 15;
        uint32_t nb = blk >> 2, kbb = blk & 3;
        b_base0 = (((uint32_t)(n0 >> 3) + nb) * 128u + kbb) * 64u + w * 4u;
        b_dst0  = A_TILE_B + blk * 256u + w * 16u;
    }
    const uint32_t a_bstride = KA8 * 128u;

    auto issue = [&](int c) {
        const uint32_t st = sb + (c % NSTAGE) * STAGE_B;
        const float* Ap = (MODE == 3 && c >= 16) ? Ap2 : Ap1;
        const uint32_t ca = (MODE == 3) ? (uint32_t)(c & 15) * 512u : (uint32_t)c * 512u;
        const uint32_t cb = (uint32_t)c * 256u;
        #pragma unroll
        for (uint32_t j = 0; j < 8; j++)
            cp16(st + a_dst0 + j * 2048u, Ap + a_base0 + j * a_bstride + ca);
        #pragma unroll
        for (uint32_t j = 0; j < 8; j++)
            cp16(st + b_dst0 + j * 2048u, Bp + b_base0 + j * 16384u + cb);
        asm volatile("cp.async.commit_group;" ::: "memory");
    };

    const uint32_t a_lds = (uint32_t)lane * 16u;
    const uint32_t b_lds = A_TILE_B + (uint32_t)lane * 8u;

    issue(0);
    issue(1);
    #pragma unroll 1
    for (int c = 0; c < NIT; c++) {
        if (c == NIT - 1) asm volatile("cp.async.wait_group 0;" ::: "memory");
        else              asm volatile("cp.async.wait_group 1;" ::: "memory");
        __syncthreads();
        if (c + 2 < NIT) issue(c + 2);

        const uint32_t base = sb + (c % NSTAGE) * STAGE_B;
        #pragma unroll
        for (int ks = 0; ks < 4; ks++) {
            uint32_t bf[8][2];
            #pragma unroll
            for (int nt = 0; nt < 8; nt++)
                lds64(bf[nt], base + b_lds + ((wn * 8 + nt) * 4 + ks) * 256u);
            #pragma unroll
            for (int mt = 0; mt < 4; mt++) {
                uint32_t af[4];
                lds128(af, base + a_lds + ((wm * 4 + mt) * 4 + ks) * 512u);
                #pragma unroll
                for (int nt = 0; nt < 8; nt++) mmatf32(acc[mt][nt], af, bf[nt]);
            }
        }
    }

    __syncthreads();

    // ---------------- epilogue ----------------
    const int g = lane >> 2, tig = lane & 3;
    float* stg = (float*)smem;
    uint32_t* stg_u = (uint32_t*)smem;

    // --- MODE 1: fused f1/f2 partial dots (from regs) ---
    if (MODE == 1) {
        const float* av = fcb;   // 'a' vector, length 2*FOUT
        #pragma unroll
        for (int mt = 0; mt < 4; mt++) {
            float f1a = 0.f, f2a = 0.f, f1b = 0.f, f2b = 0.f;
            #pragma unroll
            for (int nt = 0; nt < 8; nt++) {
                float* c = acc[mt][nt];
                const int nc = n0 + wn * 64 + nt * 8 + tig * 2;
                float a10 = av[nc], a11 = av[nc + 1];
                float a20 = av[FOUT + nc], a21 = av[FOUT + nc + 1];
                f1a += c[0] * a10 + c[1] * a11;
                f2a += c[0] * a20 + c[1] * a21;
                f1b += c[2] * a10 + c[3] * a11;
                f2b += c[2] * a20 + c[3] * a21;
            }
            f1a += __shfl_down_sync(0xffffffffu, f1a, 2, 4);
            f1a += __shfl_down_sync(0xffffffffu, f1a, 1, 4);
            f2a += __shfl_down_sync(0xffffffffu, f2a, 2, 4);
            f2a += __shfl_down_sync(0xffffffffu, f2a, 1, 4);
            f1b += __shfl_down_sync(0xffffffffu, f1b, 2, 4);
            f1b += __shfl_down_sync(0xffffffffu, f1b, 1, 4);
            f2b += __shfl_down_sync(0xffffffffu, f2b, 2, 4);
            f2b += __shfl_down_sync(0xffffffffu, f2b, 1, 4);
            if (tig == 0) {
                const int r0 = wm * 64 + mt * 16 + g, r1 = r0 + 8;
                stg[wn * 128 + r0] = f1a;  stg[wn * 128 + r1] = f1b;
                stg[256 + wn * 128 + r0] = f2a;  stg[256 + wn * 128 + r1] = f2b;
            }
        }
        __syncthreads();
        if (tid < 128) {
            d_f1p[(size_t)blockIdx.x * MTOT + m0 + tid] = stg[tid] + stg[128 + tid];
            d_f2p[(size_t)blockIdx.x * MTOT + m0 + tid] = stg[256 + tid] + stg[384 + tid];
        }
        __syncthreads();
    }

    if (MODE == 1 || MODE == 2) {
        // phase A: A-frag tile stage (8 mg x 16 kb x 128 = 65536 B)
        #pragma unroll
        for (int mt = 0; mt < 4; mt++) {
            const int lr0 = wm * 64 + mt * 16 + g;
            float s0 = 1.f, s1 = 1.f;
            if (MODE == 2) {
                s0 = d_inv[b * NN + m0 + lr0];
                s1 = d_inv[b * NN + m0 + lr0 + 8];
            }
            #pragma unroll
            for (int nt = 0; nt < 8; nt++) {
                float* c = acc[mt][nt];
                const uint32_t kb_l = wn * 8 + nt;
                const uint32_t t0 = g * 4 + ((tig * 2) & 3);
                const uint32_t basei = ((uint32_t)(wm * 4 + mt) * 16 + kb_l) * 128u
                                     + (uint32_t)(tig >> 1) * 2u;
                stg[basei + t0 * 4 + 0]       = __uint_as_float(tf32b(c[0] * s0));
                stg[basei + (t0 + 1) * 4 + 0] = __uint_as_float(tf32b(c[1] * s0));
                stg[basei + t0 * 4 + 1]       = __uint_as_float(tf32b(c[2] * s1));
                stg[basei + (t0 + 1) * 4 + 1] = __uint_as_float(tf32b(c[3] * s1));
            }
        }
        __syncthreads();
        const uint32_t MGb = (MODE == 2) ? (uint32_t)(b * NN + m0) >> 4 : (uint32_t)m0 >> 4;
        uint4* gdst = (uint4*)((MODE == 1) ? (uint32_t*)d_h_af : (uint32_t*)d_agg_af);
        for (int o4 = tid; o4 < 4096; o4 += 128) {
            uint32_t mg_l = o4 >> 9, rest = o4 & 511;
            gdst[(size_t)(MGb + mg_l) * 2048u + ((uint32_t)n0 >> 3) * 32u + rest] =
                *(uint4*)(stg + (size_t)o4 * 4u);
        }
        __syncthreads();
    }

    if (MODE == 1) {
        // phase C: h^T B-frag tile stage (16 nb x 16 kb x 64 = 65536 B)
        #pragma unroll
        for (int mt = 0; mt < 4; mt++) {
            const int r0 = wm * 64 + mt * 16 + g;   // local m
            const int r1 = r0 + 8;
            #pragma unroll
            for (int nt = 0; nt < 8; nt++) {
                float* c = acc[mt][nt];
                const int nl = wn * 64 + nt * 8 + tig * 2;   // local n
                const uint32_t i00 = (uint32_t)(nl >> 3) * 1024u + (uint32_t)(r0 >> 3) * 64u
                                   + ((uint32_t)(nl & 7) * 4u + (uint32_t)(r0 & 3)) * 2u + ((uint32_t)(r0 >> 2) & 1u);
                const uint32_t i10 = (uint32_t)((nl + 1) >> 3) * 1024u + (uint32_t)(r0 >> 3) * 64u
                                   + ((uint32_t)((nl + 1) & 7) * 4u + (uint32_t)(r0 & 3)) * 2u + ((uint32_t)(r0 >> 2) & 1u);
                const uint32_t i01 = (uint32_t)(nl >> 3) * 1024u + (uint32_t)(r1 >> 3) * 64u
                                   + ((uint32_t)(nl & 7) * 4u + (uint32_t)(r1 & 3)) * 2u + ((uint32_t)(r1 >> 2) & 1u);
                const uint32_t i11 = (uint32_t)((nl + 1) >> 3) * 1024u + (uint32_t)(r1 >> 3) * 64u
                                   + ((uint32_t)((nl + 1) & 7) * 4u + (uint32_t)(r1 & 3)) * 2u + ((uint32_t)(r1 >> 2) & 1u);
                stg_u[i00] = tf32b(c[0]);
                stg_u[i10] = tf32b(c[1]);
                stg_u[i01] = tf32b(c[2]);
                stg_u[i11] = tf32b(c[3]);
            }
        }
        __syncthreads();
        const uint32_t bb  = (uint32_t)m0 >> 10;
        const uint32_t ml0 = (uint32_t)m0 & 1023;
        uint4* gdst = (uint4*)((uint32_t*)d_ht_bf + (size_t)bb * (FOUT * NN));
        const uint4* src4 = (const uint4*)stg_u;
        for (int o4 = tid; o4 < 4096; o4 += 128) {
            uint32_t nbl = o4 >> 8, rest = o4 & 255;
            gdst[((uint32_t)(n0 >> 3) + nbl) * 2048u + (ml0 >> 3) * 16u + rest] =
                src4[nbl * 256u + rest];
        }
    }

    if (MODE == 3) {
        // phase B: linear 128x128 tile (row pad 132; 67584 B <= 98304 B)
        #pragma unroll
        for (int mt = 0; mt < 4; mt++) {
            const int lr0 = wm * 64 + mt * 16 + g;
            const int lr1 = lr0 + 8;
            #pragma unroll
            for (int nt = 0; nt < 8; nt++) {
                float* c = acc[mt][nt];
                const int lc = wn * 64 + nt * 8 + tig * 2;
                float b0 = fcb[n0 + lc], b1 = fcb[n0 + lc + 1];
                float v0 = c[0] + b0; v0 = v0 > 0.f ? v0 : expm1f(v0);
                float v1 = c[1] + b1; v1 = v1 > 0.f ? v1 : expm1f(v1);
                float v2 = c[2] + b0; v2 = v2 > 0.f ? v2 : expm1f(v2);
                float v3 = c[3] + b1; v3 = v3 > 0.f ? v3 : expm1f(v3);
                stg[lr0 * 132 + lc] = v0; stg[lr0 * 132 + lc + 1] = v1;
                stg[lr1 * 132 + lc] = v2; stg[lr1 * 132 + lc + 1] = v3;
            }
        }
        __syncthreads();
        for (int o4 = tid; o4 < 4096; o4 += 128) {
            uint32_t r = o4 >> 5, w4 = o4 & 31;
            *(uint4*)(outp + (size_t)(m0 + r) * FOUT + n0 + w4 * 4u) =
                *(uint4*)(stg + r * 132u + w4 * 4u);
        }
    }
}

// ---------------- launch -----------------------------------------------------
extern "C" void kernel_launch(void* const* d_in, const int* in_sizes, int n_in,
                              void* d_out, int out_size)
{
    const float* x   = (const float*)d_in[0];
    const int*   adj = (const int*)  d_in[1];
    const float* W   = (const float*)d_in[2];
    const float* a   = (const float*)d_in[3];
    const float* fcw = (const float*)d_in[4];
    const float* fcb = (const float*)d_in[5];
    float* out = (float*)d_out;

    cudaFuncSetAttribute(k_tc<1>, cudaFuncAttributeMaxDynamicSharedMemorySize, SM_BYTES);
    cudaFuncSetAttribute(k_tc<2>, cudaFuncAttributeMaxDynamicSharedMemorySize, SM_BYTES);
    cudaFuncSetAttribute(k_tc<3>, cudaFuncAttributeMaxDynamicSharedMemorySize, SM_BYTES);

    // conversions to fragment-major tf32
    k_cvt_x  <<<(MTOT * FIN) / 256, 256>>>(x);
    k_cvt_wt <<<(FIN * FOUT) / 256, 256>>>(W);
    k_cvt_fcw<<<(FOUT * 2 * FOUT) / 256, 256>>>(fcw);

    // 1) h = x @ W  (writes h A-frag, h^T B-frag, f1/f2 partials)
    k_tc<1><<<dim3(FOUT / 128, MTOT / 128), 128, SM_BYTES>>>(a, nullptr);
    // 1b) reduce f1/f2 partials
    k_fred<<<MTOT / 256, 256>>>();
    // 2) attention numerators (A-frag) + inverse row sums
    k_att<<<MTOT, 256>>>(adj);
    // 3) agg = softmax(att) @ h
    k_tc<2><<<dim3(FOUT / 128, NN / 128, BB), 128, SM_BYTES>>>(nullptr, nullptr);
    // 4) out = elu([agg, h] @ fc_w^T + fc_b)
    k_tc<3><<<dim3(FOUT / 128, MTOT / 128), 128, SM_BYTES>>>(fcb, out);
}

// round 17
// speedup vs baseline: 1.2467x; 1.0305x over previous
#include <cuda_runtime.h>
#include <math.h>
#include <stdint.h>

#define ALPHA_SLOPE 0.2f
#define NEG_INF_F   -9000000000000000.0f

#define BB    16
#define NN    1024
#define FIN   1024
#define FOUT  512
#define MTOT  (BB*NN)        // 16384

// ---------------- scratch: fragment-major tf32 buffers ----------------------
__device__ float d_x_af  [(size_t)MTOT * FIN];         // 64MB
__device__ float d_wt_bf [(size_t)FOUT * FIN];         // 2MB  (W^T as B-frag)
__device__ float d_fcw_bf[(size_t)FOUT * 2 * FOUT];    // 2MB
__device__ float d_h_af  [(size_t)MTOT * FOUT];        // 32MB (A-frag, K=512)
__device__ float d_ht_bf [(size_t)BB * FOUT * NN];     // 32MB (h^T B-frag per batch)
__device__ float d_att_af[(size_t)MTOT * NN];          // 64MB (A-frag per batch)
__device__ float d_agg_af[(size_t)MTOT * FOUT];        // 32MB (A-frag, K=512)
__device__ float d_f1p[4 * MTOT];                      // per-n-tile partials
__device__ float d_f2p[4 * MTOT];
__device__ float d_f1 [MTOT];
__device__ float d_f2 [MTOT];
__device__ float d_inv[MTOT];

// ---------------- helpers ----------------------------------------------------
__device__ __forceinline__ uint32_t smem_u32(const void* p) {
    uint32_t a;
    asm("{ .reg .u64 t; cvta.to.shared.u64 t, %1; cvt.u32.u64 %0, t; }" : "=r"(a) : "l"(p));
    return a;
}
__device__ __forceinline__ void cp16(uint32_t s, const void* g) {
    asm volatile("cp.async.cg.shared.global [%0], [%1], 16;" :: "r"(s), "l"(g));
}
__device__ __forceinline__ void lds128(uint32_t* r, uint32_t a) {
    asm volatile("ld.shared.v4.b32 {%0,%1,%2,%3}, [%4];"
        : "=r"(r[0]), "=r"(r[1]), "=r"(r[2]), "=r"(r[3]) : "r"(a));
}
__device__ __forceinline__ void lds64(uint32_t* r, uint32_t a) {
    asm volatile("ld.shared.v2.b32 {%0,%1}, [%2];"
        : "=r"(r[0]), "=r"(r[1]) : "r"(a));
}
__device__ __forceinline__ void mmatf32(float* c, const uint32_t* a, const uint32_t* b) {
    asm volatile("mma.sync.aligned.m16n8k8.row.col.f32.tf32.tf32.f32 "
        "{%0,%1,%2,%3}, {%4,%5,%6,%7}, {%8,%9}, {%0,%1,%2,%3};"
        : "+f"(c[0]), "+f"(c[1]), "+f"(c[2]), "+f"(c[3])
        : "r"(a[0]), "r"(a[1]), "r"(a[2]), "r"(a[3]), "r"(b[0]), "r"(b[1]));
}
__device__ __forceinline__ uint32_t tf32b(float x) {
    uint32_t u;
    asm("cvt.rna.tf32.f32 %0, %1;" : "=r"(u) : "f"(x));
    return u;
}
__device__ __forceinline__ uint32_t afrag_off(uint32_t m, uint32_t k, uint32_t KB8) {
    return ((m >> 4) * KB8 + (k >> 3)) * 128u
         + ((m & 7) * 4 + (k & 3)) * 4u + ((k >> 2) & 1) * 2u + ((m >> 3) & 1);
}
__device__ __forceinline__ uint32_t bfrag_off(uint32_t n, uint32_t k, uint32_t KB8) {
    return ((n >> 3) * KB8 + (k >> 3)) * 64u
         + ((n & 7) * 4 + (k & 3)) * 2u + ((k >> 2) & 1);
}

// ---------------- conversion kernels (max parallelism, scattered) ------------
__global__ void k_cvt_x(const float* __restrict__ x)
{
    uint32_t i = blockIdx.x * 256 + threadIdx.x;     // 16.8M
    uint32_t m = i >> 10, k = i & 1023;
    ((uint32_t*)d_x_af)[afrag_off(m, k, 128)] = tf32b(x[i]);
}
__global__ void k_cvt_wt(const float* __restrict__ W)    // W[1024][512] -> B-frag [n][k]
{
    uint32_t i = blockIdx.x * 256 + threadIdx.x;
    uint32_t n = i & 511, k = i >> 9;
    ((uint32_t*)d_wt_bf)[bfrag_off(n, k, 128)] = tf32b(W[i]);
}
__global__ void k_cvt_fcw(const float* __restrict__ FCW) // fcw[512][1024] -> B-frag
{
    uint32_t i = blockIdx.x * 256 + threadIdx.x;
    uint32_t n = i >> 10, k = i & 1023;
    ((uint32_t*)d_fcw_bf)[bfrag_off(n, k, 128)] = tf32b(FCW[i]);
}

// ---------------- f1/f2 partial reduction (4 n-tiles -> final) ---------------
__global__ void k_fred()
{
    int r = blockIdx.x * 256 + threadIdx.x;
    d_f1[r] = d_f1p[r] + d_f1p[MTOT + r] + d_f1p[2 * MTOT + r] + d_f1p[3 * MTOT + r];
    d_f2[r] = d_f2p[r] + d_f2p[MTOT + r] + d_f2p[2 * MTOT + r] + d_f2p[3 * MTOT + r];
}

// ---------------- attention: warp-per-row, barrier-free ----------------------
__global__ void k_att(const int* __restrict__ adj)
{
    const int lane = threadIdx.x & 31;
    const int row  = blockIdx.x * 8 + (threadIdx.x >> 5);
    const int b    = row >> 10;
    const uint32_t iloc = row & 1023;

    const float f1i = d_f1[row];
    const int4*   arow = (const int4*)(adj + (size_t)row * NN);
    const float4* f2b4 = (const float4*)(d_f2 + b * NN);

    float4 ev[8];
    float lmax = -INFINITY;
    #pragma unroll
    for (int it = 0; it < 8; it++) {
        const int q = lane + it * 32;
        int4   av = __ldg(arow + q);
        float4 fv = __ldg(f2b4 + q);
        float4 e;
        e.x = f1i + fv.x; e.x = e.x > 0.f ? e.x : ALPHA_SLOPE * e.x; if (av.x <= 0) e.x = NEG_INF_F;
        e.y = f1i + fv.y; e.y = e.y > 0.f ? e.y : ALPHA_SLOPE * e.y; if (av.y <= 0) e.y = NEG_INF_F;
        e.z = f1i + fv.z; e.z = e.z > 0.f ? e.z : ALPHA_SLOPE * e.z; if (av.z <= 0) e.z = NEG_INF_F;
        e.w = f1i + fv.w; e.w = e.w > 0.f ? e.w : ALPHA_SLOPE * e.w; if (av.w <= 0) e.w = NEG_INF_F;
        ev[it] = e;
        lmax = fmaxf(lmax, fmaxf(fmaxf(e.x, e.y), fmaxf(e.z, e.w)));
    }
    #pragma unroll
    for (int o = 16; o; o >>= 1) lmax = fmaxf(lmax, __shfl_xor_sync(0xffffffffu, lmax, o));

    float lsum = 0.f;
    uint32_t* pA = (uint32_t*)d_att_af + (size_t)b * (NN * NN);
    const uint32_t rowbase = (iloc >> 4) * (128u * 128u) + (iloc & 7) * 16u + ((iloc >> 3) & 1);
    #pragma unroll
    for (int it = 0; it < 8; it++) {
        const int q = lane + it * 32;
        float4 e = ev[it];
        float p0 = __expf(e.x - lmax);
        float p1 = __expf(e.y - lmax);
        float p2 = __expf(e.z - lmax);
        float p3 = __expf(e.w - lmax);
        const uint32_t base = rowbase + (uint32_t)(q >> 1) * 128u + (uint32_t)(q & 1) * 2u;
        pA[base]      = tf32b(p0);
        pA[base + 4]  = tf32b(p1);
        pA[base + 8]  = tf32b(p2);
        pA[base + 12] = tf32b(p3);
        lsum += (p0 + p1) + (p2 + p3);
    }
    #pragma unroll
    for (int o = 16; o; o >>= 1) lsum += __shfl_xor_sync(0xffffffffu, lsum, o);
    if (lane == 0) d_inv[row] = 1.f / lsum;
}

// ---------------- tf32 mma GEMM: 128x128 tile, 4 warps of 64x64, BK=32 -------
// 3 stages x 32KB = 96KB smem -> 2 CTAs/SM; regs ~255 (launch_bounds(128,2))
#define A_TILE_B 16384
#define STAGE_B  32768
#define NSTAGE   3
#define SM_BYTES (NSTAGE * STAGE_B)    // 98304 -> 2 CTAs/SM

template<int MODE>
__global__ __launch_bounds__(128, 2)
void k_tc(const float* __restrict__ fcb, float* __restrict__ outp)
{
    extern __shared__ char smem[];
    const uint32_t sb = smem_u32(smem);
    const int tid = threadIdx.x;
    const int wid = tid >> 5, lane = tid & 31;
    const int wm = wid & 1, wn = wid >> 1;       // 2 x 2 warp grid; warp tile 64m x 64n

    const int n0 = blockIdx.x * 128;
    const int m0 = blockIdx.y * 128;             // local row for MODE 2, global else
    const int b  = (MODE == 2) ? blockIdx.z : (m0 >> 10);

    float acc[4][8][4] = {};
    const int NIT = 32;                          // K = 1024, BK = 32

    const float *Ap1, *Ap2, *Bp;
    uint32_t KA8;
    if (MODE == 1) {
        Ap1 = d_x_af;  Ap2 = Ap1; Bp = d_wt_bf;  KA8 = 128;
    } else if (MODE == 2) {
        Ap1 = d_att_af + (uint32_t)b * (NN * NN); Ap2 = Ap1;
        Bp  = d_ht_bf  + (uint32_t)b * (FOUT * NN); KA8 = 128;
    } else {
        Ap1 = d_agg_af; Ap2 = d_h_af; Bp = d_fcw_bf; KA8 = 64;
    }

    uint32_t a_base0, a_dst0, b_base0, b_dst0;
    {
        uint32_t blk = (uint32_t)tid >> 5, w = (uint32_t)tid & 31;
        uint32_t mb = blk >> 2, kb = blk & 3;
        a_base0 = (((uint32_t)(m0 >> 4) + mb) * KA8 + kb) * 128u + w * 4u;
        a_dst0  = blk * 512u + w * 16u;
        blk = (uint32_t)tid >> 4; w = (uint32_t)tid & 15;
        uint32_t nb = blk >> 2, kbb = blk & 3;
        b_base0 = (((uint32_t)(n0 >> 3) + nb) * 128u + kbb) * 64u + w * 4u;
        b_dst0  = A_TILE_B + blk * 256u + w * 16u;
    }
    const uint32_t a_bstride = KA8 * 128u;

    auto issue = [&](int c) {
        const uint32_t st = sb + (c % NSTAGE) * STAGE_B;
        const float* Ap = (MODE == 3 && c >= 16) ? Ap2 : Ap1;
        const uint32_t ca = (MODE == 3) ? (uint32_t)(c & 15) * 512u : (uint32_t)c * 512u;
        const uint32_t cb = (uint32_t)c * 256u;
        #pragma unroll
        for (uint32_t j = 0; j < 8; j++)
            cp16(st + a_dst0 + j * 2048u, Ap + a_base0 + j * a_bstride + ca);
        #pragma unroll
        for (uint32_t j = 0; j < 8; j++)
            cp16(st + b_dst0 + j * 2048u, Bp + b_base0 + j * 16384u + cb);
        asm volatile("cp.async.commit_group;" ::: "memory");
    };

    const uint32_t a_lds = (uint32_t)lane * 16u;
    const uint32_t b_lds = A_TILE_B + (uint32_t)lane * 8u;

    issue(0);
    issue(1);
    #pragma unroll 1
    for (int c = 0; c < NIT; c++) {
        if (c == NIT - 1) asm volatile("cp.async.wait_group 0;" ::: "memory");
        else              asm volatile("cp.async.wait_group 1;" ::: "memory");
        __syncthreads();
        if (c + 2 < NIT) issue(c + 2);

        const uint32_t base = sb + (c % NSTAGE) * STAGE_B;
        #pragma unroll
        for (int ks = 0; ks < 4; ks++) {
            uint32_t bf[8][2];
            #pragma unroll
            for (int nt = 0; nt < 8; nt++)
                lds64(bf[nt], base + b_lds + ((wn * 8 + nt) * 4 + ks) * 256u);
            #pragma unroll
            for (int mt = 0; mt < 4; mt++) {
                uint32_t af[4];
                lds128(af, base + a_lds + ((wm * 4 + mt) * 4 + ks) * 512u);
                #pragma unroll
                for (int nt = 0; nt < 8; nt++) mmatf32(acc[mt][nt], af, bf[nt]);
            }
        }
    }

    __syncthreads();

    // ---------------- epilogue ----------------
    const int g = lane >> 2, tig = lane & 3;
    float* stg = (float*)smem;
    uint32_t* stg_u = (uint32_t*)smem;

    // --- MODE 1: fused f1/f2 partial dots (from regs) ---
    if (MODE == 1) {
        const float* av = fcb;   // 'a' vector, length 2*FOUT
        #pragma unroll
        for (int mt = 0; mt < 4; mt++) {
            float f1a = 0.f, f2a = 0.f, f1b = 0.f, f2b = 0.f;
            #pragma unroll
            for (int nt = 0; nt < 8; nt++) {
                float* c = acc[mt][nt];
                const int nc = n0 + wn * 64 + nt * 8 + tig * 2;
                float a10 = av[nc], a11 = av[nc + 1];
                float a20 = av[FOUT + nc], a21 = av[FOUT + nc + 1];
                f1a += c[0] * a10 + c[1] * a11;
                f2a += c[0] * a20 + c[1] * a21;
                f1b += c[2] * a10 + c[3] * a11;
                f2b += c[2] * a20 + c[3] * a21;
            }
            f1a += __shfl_down_sync(0xffffffffu, f1a, 2, 4);
            f1a += __shfl_down_sync(0xffffffffu, f1a, 1, 4);
            f2a += __shfl_down_sync(0xffffffffu, f2a, 2, 4);
            f2a += __shfl_down_sync(0xffffffffu, f2a, 1, 4);
            f1b += __shfl_down_sync(0xffffffffu, f1b, 2, 4);
            f1b += __shfl_down_sync(0xffffffffu, f1b, 1, 4);
            f2b += __shfl_down_sync(0xffffffffu, f2b, 2, 4);
            f2b += __shfl_down_sync(0xffffffffu, f2b, 1, 4);
            if (tig == 0) {
                const int r0 = wm * 64 + mt * 16 + g, r1 = r0 + 8;
                stg[wn * 128 + r0] = f1a;  stg[wn * 128 + r1] = f1b;
                stg[256 + wn * 128 + r0] = f2a;  stg[256 + wn * 128 + r1] = f2b;
            }
        }
        __syncthreads();
        if (tid < 128) {
            d_f1p[(size_t)blockIdx.x * MTOT + m0 + tid] = stg[tid] + stg[128 + tid];
            d_f2p[(size_t)blockIdx.x * MTOT + m0 + tid] = stg[256 + tid] + stg[384 + tid];
        }
        __syncthreads();
    }

    if (MODE == 1 || MODE == 2) {
        // phase A: A-frag tile stage (8 mg x 16 kb x 128 = 65536 B)
        #pragma unroll
        for (int mt = 0; mt < 4; mt++) {
            const int lr0 = wm * 64 + mt * 16 + g;
            float s0 = 1.f, s1 = 1.f;
            if (MODE == 2) {
                s0 = d_inv[b * NN + m0 + lr0];
                s1 = d_inv[b * NN + m0 + lr0 + 8];
            }
            #pragma unroll
            for (int nt = 0; nt < 8; nt++) {
                float* c = acc[mt][nt];
                const uint32_t kb_l = wn * 8 + nt;
                const uint32_t t0 = g * 4 + ((tig * 2) & 3);
                const uint32_t basei = ((uint32_t)(wm * 4 + mt) * 16 + kb_l) * 128u
                                     + (uint32_t)(tig >> 1) * 2u;
                stg[basei + t0 * 4 + 0]       = __uint_as_float(tf32b(c[0] * s0));
                stg[basei + (t0 + 1) * 4 + 0] = __uint_as_float(tf32b(c[1] * s0));
                stg[basei + t0 * 4 + 1]       = __uint_as_float(tf32b(c[2] * s1));
                stg[basei + (t0 + 1) * 4 + 1] = __uint_as_float(tf32b(c[3] * s1));
            }
        }
        __syncthreads();
        const uint32_t MGb = (MODE == 2) ? (uint32_t)(b * NN + m0) >> 4 : (uint32_t)m0 >> 4;
        uint4* gdst = (uint4*)((MODE == 1) ? (uint32_t*)d_h_af : (uint32_t*)d_agg_af);
        for (int o4 = tid; o4 < 4096; o4 += 128) {
            uint32_t mg_l = o4 >> 9, rest = o4 & 511;
            gdst[(size_t)(MGb + mg_l) * 2048u + ((uint32_t)n0 >> 3) * 32u + rest] =
                *(uint4*)(stg + (size_t)o4 * 4u);
        }
        __syncthreads();
    }

    if (MODE == 1) {
        // phase C: h^T B-frag tile stage (16 nb x 16 kb x 64 = 65536 B)
        #pragma unroll
        for (int mt = 0; mt < 4; mt++) {
            const int r0 = wm * 64 + mt * 16 + g;   // local m
            const int r1 = r0 + 8;
            #pragma unroll
            for (int nt = 0; nt < 8; nt++) {
                float* c = acc[mt][nt];
                const int nl = wn * 64 + nt * 8 + tig * 2;   // local n
                const uint32_t i00 = (uint32_t)(nl >> 3) * 1024u + (uint32_t)(r0 >> 3) * 64u
                                   + ((uint32_t)(nl & 7) * 4u + (uint32_t)(r0 & 3)) * 2u + ((uint32_t)(r0 >> 2) & 1u);
                const uint32_t i10 = (uint32_t)((nl + 1) >> 3) * 1024u + (uint32_t)(r0 >> 3) * 64u
                                   + ((uint32_t)((nl + 1) & 7) * 4u + (uint32_t)(r0 & 3)) * 2u + ((uint32_t)(r0 >> 2) & 1u);
                const uint32_t i01 = (uint32_t)(nl >> 3) * 1024u + (uint32_t)(r1 >> 3) * 64u
                                   + ((uint32_t)(nl & 7) * 4u + (uint32_t)(r1 & 3)) * 2u + ((uint32_t)(r1 >> 2) & 1u);
                const uint32_t i11 = (uint32_t)((nl + 1) >> 3) * 1024u + (uint32_t)(r1 >> 3) * 64u
                                   + ((uint32_t)((nl + 1) & 7) * 4u + (uint32_t)(r1 & 3)) * 2u + ((uint32_t)(r1 >> 2) & 1u);
                stg_u[i00] = tf32b(c[0]);
                stg_u[i10] = tf32b(c[1]);
                stg_u[i01] = tf32b(c[2]);
                stg_u[i11] = tf32b(c[3]);
            }
        }
        __syncthreads();
        const uint32_t bb  = (uint32_t)m0 >> 10;
        const uint32_t ml0 = (uint32_t)m0 & 1023;
        uint4* gdst = (uint4*)((uint32_t*)d_ht_bf + (size_t)bb * (FOUT * NN));
        const uint4* src4 = (const uint4*)stg_u;
        for (int o4 = tid; o4 < 4096; o4 += 128) {
            uint32_t nbl = o4 >> 8, rest = o4 & 255;
            gdst[((uint32_t)(n0 >> 3) + nbl) * 2048u + (ml0 >> 3) * 16u + rest] =
                src4[nbl * 256u + rest];
        }
    }

    if (MODE == 3) {
        // phase B: linear 128x128 tile (row pad 132; 67584 B <= 98304 B)
        #pragma unroll
        for (int mt = 0; mt < 4; mt++) {
            const int lr0 = wm * 64 + mt * 16 + g;
            const int lr1 = lr0 + 8;
            #pragma unroll
            for (int nt = 0; nt < 8; nt++) {
                float* c = acc[mt][nt];
                const int lc = wn * 64 + nt * 8 + tig * 2;
                float b0 = fcb[n0 + lc], b1 = fcb[n0 + lc + 1];
                float v0 = c[0] + b0; v0 = v0 > 0.f ? v0 : expm1f(v0);
                float v1 = c[1] + b1; v1 = v1 > 0.f ? v1 : expm1f(v1);
                float v2 = c[2] + b0; v2 = v2 > 0.f ? v2 : expm1f(v2);
                float v3 = c[3] + b1; v3 = v3 > 0.f ? v3 : expm1f(v3);
                stg[lr0 * 132 + lc] = v0; stg[lr0 * 132 + lc + 1] = v1;
                stg[lr1 * 132 + lc] = v2; stg[lr1 * 132 + lc + 1] = v3;
            }
        }
        __syncthreads();
        for (int o4 = tid; o4 < 4096; o4 += 128) {
            uint32_t r = o4 >> 5, w4 = o4 & 31;
            *(uint4*)(outp + (size_t)(m0 + r) * FOUT + n0 + w4 * 4u) =
                *(uint4*)(stg + r * 132u + w4 * 4u);
        }
    }
}

// ---------------- launch -----------------------------------------------------
extern "C" void kernel_launch(void* const* d_in, const int* in_sizes, int n_in,
                              void* d_out, int out_size)
{
    const float* x   = (const float*)d_in[0];
    const int*   adj = (const int*)  d_in[1];
    const float* W   = (const float*)d_in[2];
    const float* a   = (const float*)d_in[3];
    const float* fcw = (const float*)d_in[4];
    const float* fcb = (const float*)d_in[5];
    float* out = (float*)d_out;

    cudaFuncSetAttribute(k_tc<1>, cudaFuncAttributeMaxDynamicSharedMemorySize, SM_BYTES);
    cudaFuncSetAttribute(k_tc<2>, cudaFuncAttributeMaxDynamicSharedMemorySize, SM_BYTES);
    cudaFuncSetAttribute(k_tc<3>, cudaFuncAttributeMaxDynamicSharedMemorySize, SM_BYTES);

    // conversions to fragment-major tf32
    k_cvt_x  <<<(MTOT * FIN) / 256, 256>>>(x);
    k_cvt_wt <<<(FIN * FOUT) / 256, 256>>>(W);
    k_cvt_fcw<<<(FOUT * 2 * FOUT) / 256, 256>>>(fcw);

    // 1) h = x @ W  (writes h A-frag, h^T B-frag, f1/f2 partials)
    k_tc<1><<<dim3(FOUT / 128, MTOT / 128), 128, SM_BYTES>>>(a, nullptr);
    // 1b) reduce f1/f2 partials
    k_fred<<<MTOT / 256, 256>>>();
    // 2) attention numerators (A-frag) + inverse row sums  (warp per row)
    k_att<<<MTOT / 8, 256>>>(adj);
    // 3) agg = softmax(att) @ h
    k_tc<2><<<dim3(FOUT / 128, NN / 128, BB), 128, SM_BYTES>>>(nullptr, nullptr);
    // 4) out = elu([agg, h] @ fc_w^T + fc_b)
    k_tc<3><<<dim3(FOUT / 128, MTOT / 128), 128, SM_BYTES>>>(fcb, out);
}